// round 8
// baseline (speedup 1.0000x reference)
#include <cuda_runtime.h>
#include <cstdint>

// ---------------- constants ----------------
#define Bn 32
#define Mn 448
#define Cn 384
#define Sn 512
#define SDn 128
#define Kn 8
#define NROWS (Bn * Sn)   // 16384

// ---------------- scratch ----------------
__device__ int      g_idx[NROWS * Kn];
__device__ float    g_X[NROWS * 64];         // h1(relu) only, stride 64
__device__ unsigned g_proxy[Bn * SDn];       // encoded float max
__device__ float    g_g2qc[Bn * 1408];       // [0:1024]=g2, [1024:1408]=qc
__device__ float    g_g1[Bn * 1024];
__device__ float    g_base[Bn * Cn];         // atomic-accumulated base (excl. red_b)
__device__ float    g_sink;                  // prefetch sink (never read)

// ---------------- helpers ----------------
__device__ __forceinline__ unsigned fenc(float f) {
    unsigned u = __float_as_uint(f);
    return (u & 0x80000000u) ? ~u : (u | 0x80000000u);
}
__device__ __forceinline__ float fdec(unsigned e) {
    unsigned u = (e & 0x80000000u) ? (e ^ 0x80000000u) : ~e;
    return __uint_as_float(u);
}

// ================= K0: fused knn + gc1  (+ L2 weight prefetch blocks at grid.y==4) =================
__global__ __launch_bounds__(512) void knn_gc1_kernel(const float* __restrict__ skel,
                                                      const float* __restrict__ wroot,
                                                      const float* __restrict__ wrel,
                                                      const float* __restrict__ bias,
                                                      const float* __restrict__ proj_w,
                                                      const float* __restrict__ attn_in_w,
                                                      const float* __restrict__ attn_out_w,
                                                      const float* __restrict__ inc1_w,
                                                      const float* __restrict__ inc2_w,
                                                      const float* __restrict__ red_w) {
    if (blockIdx.y == 4) {
        // ---- prefetch blocks: pull downstream weights into L2 ----
        int gtid = blockIdx.x * 512 + threadIdx.x;       // 0 .. 16383
        const int gstride = Bn * 512;                    // 16384
        float4 acc = make_float4(0.f, 0.f, 0.f, 0.f);
        const float4* arrs[6] = {
            (const float4*)proj_w,                        // 128*384
            (const float4*)(attn_in_w + 2 * Cn * Cn),     // C*C (v slice)
            (const float4*)attn_out_w,                    // C*C
            (const float4*)inc1_w,                        // 1024*384
            (const float4*)inc2_w,                        // 1024*1024
            (const float4*)red_w                          // 1411*384
        };
        const int n4s[6] = { (SDn * Cn) / 4, (Cn * Cn) / 4, (Cn * Cn) / 4,
                             (1024 * Cn) / 4, (1024 * 1024) / 4, (1411 * Cn) / 4 };
        #pragma unroll
        for (int a = 0; a < 6; a++) {
            const float4* p = arrs[a];
            int n4 = n4s[a];
            for (int i = gtid; i < n4; i += gstride) {
                float4 v = __ldg(p + i);
                acc.x += v.x; acc.y += v.y; acc.z += v.z; acc.w += v.w;
            }
        }
        float s = acc.x + acc.y + acc.z + acc.w;
        if (s == 1.2345678e-30f) g_sink = s;   // keep loads observable
        return;
    }

    __shared__ float sx[Sn], sy[Sn], sz[Sn];
    __shared__ float cd[128 * 32];
    __shared__ int   ci[128 * 32];
    __shared__ float wgt[448];
    int b = blockIdx.x;
    int t = threadIdx.x;
    const float* sk = skel + (size_t)b * Sn * 3;

    #pragma unroll
    for (int q = t; q < Sn * 3; q += 512) {
        float v = sk[q];
        int idx = q / 3, r = q - idx * 3;
        if (r == 0) sx[idx] = v; else if (r == 1) sy[idx] = v; else sz[idx] = v;
    }
    if (blockIdx.y == 0 && t < SDn) g_proxy[b * SDn + t] = 0u;
    if (t < 448) wgt[t] = (t < 192) ? wroot[t] : ((t < 384) ? wrel[t - 192] : bias[t - 384]);
    __syncthreads();

    int p = t >> 2, s4 = t & 3;
    int i = blockIdx.y * 128 + p;
    float xi = sx[i], yi = sy[i], zi = sz[i];

    float bd[8]; int bi8[8];
    #pragma unroll
    for (int k = 0; k < 8; k++) { bd[k] = 3.0e38f; bi8[k] = 0; }

    for (int jj = 0; jj < 128; jj++) {
        int j = jj * 4 + s4;
        float dx = xi - sx[j], dy = yi - sy[j], dz = zi - sz[j];
        float d = fmaf(dx, dx, fmaf(dy, dy, dz * dz));
        if (j == i) d = 3.0e38f;
        if (d < bd[7]) {
            bd[7] = d; bi8[7] = j;
            #pragma unroll
            for (int k = 7; k > 0; k--) {
                if (bd[k] < bd[k - 1]) {
                    float td = bd[k]; bd[k] = bd[k - 1]; bd[k - 1] = td;
                    int ti = bi8[k]; bi8[k] = bi8[k - 1]; bi8[k - 1] = ti;
                }
            }
        }
    }
    #pragma unroll
    for (int k = 0; k < 8; k++) { cd[p * 32 + s4 * 8 + k] = bd[k]; ci[p * 32 + s4 * 8 + k] = bi8[k]; }
    __syncthreads();

    if (t < 128) {
        float fd[8]; int fi[8];
        #pragma unroll
        for (int k = 0; k < 8; k++) { fd[k] = 3.0e38f; fi[k] = 0; }
        for (int s = 0; s < 4; s++) {
            #pragma unroll
            for (int k = 0; k < 8; k++) {
                float d = cd[t * 32 + s * 8 + k];
                if (d >= fd[7]) break;
                int j = ci[t * 32 + s * 8 + k];
                fd[7] = d; fi[7] = j;
                #pragma unroll
                for (int m = 7; m > 0; m--) {
                    if (fd[m] < fd[m - 1]) {
                        float td = fd[m]; fd[m] = fd[m - 1]; fd[m - 1] = td;
                        int ti = fi[m]; fi[m] = fi[m - 1]; fi[m - 1] = ti;
                    }
                }
            }
        }
        int ip = blockIdx.y * 128 + t;
        int row = b * Sn + ip;
        float a0 = 0.f, a1 = 0.f, a2 = 0.f;
        #pragma unroll
        for (int k = 0; k < 8; k++) {
            int j = fi[k];
            g_idx[row * Kn + k] = j;
            a0 += sx[j]; a1 += sy[j]; a2 += sz[j];
        }
        float x0 = sx[ip], x1 = sy[ip], x2 = sz[ip];
        float* cif = (float*)ci;
        #pragma unroll
        for (int ch = 0; ch < 64; ch++) {
            float h = wgt[384 + ch];
            h = fmaf(x0, wgt[0 * 64 + ch], h);
            h = fmaf(x1, wgt[1 * 64 + ch], h);
            h = fmaf(x2, wgt[2 * 64 + ch], h);
            h = fmaf(a0, wgt[192 + 0 * 64 + ch], h);
            h = fmaf(a1, wgt[192 + 1 * 64 + ch], h);
            h = fmaf(a2, wgt[192 + 2 * 64 + ch], h);
            h = fmaxf(h, 0.f);
            if (ch < 32) cd[t * 32 + ch] = h; else cif[t * 32 + ch - 32] = h;
        }
    }
    __syncthreads();

    float* cif = (float*)ci;
    #pragma unroll
    for (int q = t; q < 128 * 64; q += 512) {
        int p2 = q >> 6, ch = q & 63;
        float v = (ch < 32) ? cd[p2 * 32 + ch] : cif[p2 * 32 + ch - 32];
        g_X[(size_t)(b * Sn + blockIdx.y * 128 + p2) * 64 + ch] = v;
    }
}

// ================= K1: fused agg + gc2 GEMM (128x128 tile) + per-batch column max =================
__global__ __launch_bounds__(256) void gc2_kernel(const float* __restrict__ wroot2,
                                                  const float* __restrict__ wrel2,
                                                  const float* __restrict__ b2) {
    __shared__ __align__(16) float As[64 * 132];
    __shared__ __align__(16) float Hs[16 * 132];
    __shared__ __align__(16) float Ws[16 * 128];
    int r0 = blockIdx.x * 128;
    int b = r0 >> 9;
    int tid = threadIdx.x;

    {
        int row = tid >> 1, half = tid & 1;
        const int* id = g_idx + (size_t)(r0 + row) * Kn;
        float4 acc[8];
        #pragma unroll
        for (int q = 0; q < 8; q++) acc[q] = make_float4(0.f, 0.f, 0.f, 0.f);
        #pragma unroll
        for (int n = 0; n < 8; n++) {
            int j = id[n];
            const float4* src = (const float4*)(g_X + (size_t)(b * 512 + j) * 64 + half * 32);
            #pragma unroll
            for (int q = 0; q < 8; q++) {
                float4 v = src[q];
                acc[q].x += v.x; acc[q].y += v.y; acc[q].z += v.z; acc[q].w += v.w;
            }
        }
        #pragma unroll
        for (int q = 0; q < 8; q++) {
            int c = half * 32 + q * 4;
            As[(c + 0) * 132 + row] = acc[q].x;
            As[(c + 1) * 132 + row] = acc[q].y;
            As[(c + 2) * 132 + row] = acc[q].z;
            As[(c + 3) * 132 + row] = acc[q].w;
        }
    }
    __syncthreads();

    int ty = tid >> 4, tx = tid & 15;
    float acc[8][8];
    #pragma unroll
    for (int i = 0; i < 8; i++)
        #pragma unroll
        for (int j = 0; j < 8; j++) acc[i][j] = 0.f;

    for (int ch = 0; ch < 8; ch++) {
        const float* Bsrc;
        if (ch < 4) {
            int kc = ch * 16;
            #pragma unroll
            for (int it = 0; it < 2; it++) {
                int q = it * 256 + tid;
                int r = q >> 2, quad = q & 3;
                float4 v = *(const float4*)(g_X + (size_t)(r0 + r) * 64 + kc + quad * 4);
                Hs[(quad * 4 + 0) * 132 + r] = v.x;
                Hs[(quad * 4 + 1) * 132 + r] = v.y;
                Hs[(quad * 4 + 2) * 132 + r] = v.z;
                Hs[(quad * 4 + 3) * 132 + r] = v.w;
            }
            Bsrc = Hs;
        } else {
            Bsrc = As + (ch - 4) * 16 * 132;
        }
        const float* W = (ch < 4) ? (wroot2 + (size_t)ch * 16 * 128)
                                  : (wrel2 + (size_t)(ch - 4) * 16 * 128);
        #pragma unroll
        for (int it = 0; it < 2; it++) {
            int q = it * 256 + tid;
            int k = q >> 5, c4 = q & 31;
            *(float4*)(Ws + k * 128 + c4 * 4) = *(const float4*)(W + (size_t)k * 128 + c4 * 4);
        }
        __syncthreads();
        #pragma unroll
        for (int k = 0; k < 16; k++) {
            float a[8], bv[8];
            *(float4*)(a)      = *(const float4*)(Bsrc + k * 132 + ty * 8);
            *(float4*)(a + 4)  = *(const float4*)(Bsrc + k * 132 + ty * 8 + 4);
            *(float4*)(bv)     = *(const float4*)(Ws + k * 128 + tx * 8);
            *(float4*)(bv + 4) = *(const float4*)(Ws + k * 128 + tx * 8 + 4);
            #pragma unroll
            for (int i = 0; i < 8; i++)
                #pragma unroll
                for (int j = 0; j < 8; j++)
                    acc[i][j] = fmaf(a[i], bv[j], acc[i][j]);
        }
        __syncthreads();
    }

    float* red = Ws;
    #pragma unroll
    for (int j = 0; j < 8; j++) {
        float m = acc[0][j];
        #pragma unroll
        for (int i = 1; i < 8; i++) m = fmaxf(m, acc[i][j]);
        red[ty * 128 + tx * 8 + j] = m;
    }
    __syncthreads();
    if (tid < 128) {
        float m = red[tid];
        #pragma unroll
        for (int t = 1; t < 16; t++) m = fmaxf(m, red[t * 128 + tid]);
        m += b2[tid];
        atomicMax(&g_proxy[b * SDn + tid], fenc(m));
    }
}

// ================= K2: per-batch chain proxy->kv->vh->qc (+ zero g_base) =================
__global__ __launch_bounds__(384) void chain1_kernel(const float* __restrict__ proj_w, const float* __restrict__ proj_b,
                              const float* __restrict__ attn_in_w, const float* __restrict__ attn_in_b,
                              const float* __restrict__ attn_out_w, const float* __restrict__ attn_out_b) {
    int b = blockIdx.x;
    int tid = threadIdx.x; // 384
    __shared__ float sp[SDn], skv[Cn], svh[Cn];
    if (tid < SDn) sp[tid] = fdec(g_proxy[b * SDn + tid]);
    g_base[b * Cn + tid] = 0.f;
    __syncthreads();

    float acc = proj_b[tid];
    #pragma unroll 8
    for (int k = 0; k < SDn; k++) acc = fmaf(sp[k], proj_w[k * Cn + tid], acc);
    skv[tid] = acc;
    __syncthreads();

    int w = tid >> 5, l = tid & 31;

    for (int t = 0; t < 8; t++) {
        int c0 = w * 32 + t * 4;
        const float* r0 = attn_in_w + (size_t)(2 * Cn + c0) * Cn;
        float p0 = 0.f, p1 = 0.f, p2 = 0.f, p3 = 0.f;
        #pragma unroll
        for (int j = l; j < Cn; j += 32) {
            float s = skv[j];
            p0 = fmaf(s, r0[j], p0);
            p1 = fmaf(s, r0[Cn + j], p1);
            p2 = fmaf(s, r0[2 * Cn + j], p2);
            p3 = fmaf(s, r0[3 * Cn + j], p3);
        }
        #pragma unroll
        for (int off = 16; off; off >>= 1) {
            p0 += __shfl_xor_sync(0xffffffffu, p0, off);
            p1 += __shfl_xor_sync(0xffffffffu, p1, off);
            p2 += __shfl_xor_sync(0xffffffffu, p2, off);
            p3 += __shfl_xor_sync(0xffffffffu, p3, off);
        }
        if (l == 0) {
            svh[c0 + 0] = p0 + attn_in_b[2 * Cn + c0 + 0];
            svh[c0 + 1] = p1 + attn_in_b[2 * Cn + c0 + 1];
            svh[c0 + 2] = p2 + attn_in_b[2 * Cn + c0 + 2];
            svh[c0 + 3] = p3 + attn_in_b[2 * Cn + c0 + 3];
        }
    }
    __syncthreads();

    for (int t = 0; t < 8; t++) {
        int c0 = w * 32 + t * 4;
        const float* r0 = attn_out_w + (size_t)c0 * Cn;
        float p0 = 0.f, p1 = 0.f, p2 = 0.f, p3 = 0.f;
        #pragma unroll
        for (int j = l; j < Cn; j += 32) {
            float s = svh[j];
            p0 = fmaf(s, r0[j], p0);
            p1 = fmaf(s, r0[Cn + j], p1);
            p2 = fmaf(s, r0[2 * Cn + j], p2);
            p3 = fmaf(s, r0[3 * Cn + j], p3);
        }
        #pragma unroll
        for (int off = 16; off; off >>= 1) {
            p0 += __shfl_xor_sync(0xffffffffu, p0, off);
            p1 += __shfl_xor_sync(0xffffffffu, p1, off);
            p2 += __shfl_xor_sync(0xffffffffu, p2, off);
            p3 += __shfl_xor_sync(0xffffffffu, p3, off);
        }
        if (l == 0) {
            g_g2qc[b * 1408 + 1024 + c0 + 0] = p0 + attn_out_b[c0 + 0];
            g_g2qc[b * 1408 + 1024 + c0 + 1] = p1 + attn_out_b[c0 + 1];
            g_g2qc[b * 1408 + 1024 + c0 + 2] = p2 + attn_out_b[c0 + 2];
            g_g2qc[b * 1408 + 1024 + c0 + 3] = p3 + attn_out_b[c0 + 3];
        }
    }
}

// ================= stageM: Y[8 batches][32 outs/block] = act(X @ W^T + b) =================
template<int K, int ACT>
__global__ __launch_bounds__(256) void stageM_kernel(const float* __restrict__ X, int XS,
                                                     const float* __restrict__ W,
                                                     const float* __restrict__ bias,
                                                     float* __restrict__ Y, int YS,
                                                     const float* __restrict__ bn_g,
                                                     const float* __restrict__ bn_b,
                                                     const float* __restrict__ bn_m,
                                                     const float* __restrict__ bn_v) {
    constexpr int XQ = K / 4;
    constexpr int RED_FLOATS = 8 * 32 * 33;
    constexpr int SMEM_FLOATS = (8 * K > RED_FLOATS) ? 8 * K : RED_FLOATS;
    __shared__ __align__(16) float smem[SMEM_FLOATS];
    float4* Xs = (float4*)smem;
    int tid = threadIdx.x;
    int bg = blockIdx.y;
    int w = tid >> 5, l = tid & 31;

    for (int q = tid; q < 8 * XQ; q += 256) {
        int bb = q / XQ, kq = q % XQ;
        Xs[q] = *(const float4*)(X + (size_t)(bg * 8 + bb) * XS + kq * 4);
    }
    __syncthreads();

    int o0 = blockIdx.x * 32 + w * 4;
    float acc[4][8];
    #pragma unroll
    for (int u = 0; u < 4; u++)
        #pragma unroll
        for (int bb = 0; bb < 8; bb++) acc[u][bb] = 0.f;

    #pragma unroll
    for (int ki = 0; ki < K / 128; ki++) {
        int kq = ki * 32 + l;
        float4 xv[8];
        #pragma unroll
        for (int bb = 0; bb < 8; bb++) xv[bb] = Xs[bb * XQ + kq];
        float4 wv[4];
        #pragma unroll
        for (int u = 0; u < 4; u++)
            wv[u] = *(const float4*)(W + (size_t)(o0 + u) * K + kq * 4);
        #pragma unroll
        for (int u = 0; u < 4; u++)
            #pragma unroll
            for (int bb = 0; bb < 8; bb++) {
                acc[u][bb] = fmaf(wv[u].x, xv[bb].x, acc[u][bb]);
                acc[u][bb] = fmaf(wv[u].y, xv[bb].y, acc[u][bb]);
                acc[u][bb] = fmaf(wv[u].z, xv[bb].z, acc[u][bb]);
                acc[u][bb] = fmaf(wv[u].w, xv[bb].w, acc[u][bb]);
            }
    }
    __syncthreads();

    float* red = smem;
    #pragma unroll
    for (int u = 0; u < 4; u++)
        #pragma unroll
        for (int bb = 0; bb < 8; bb++)
            red[(w * 32 + u * 8 + bb) * 33 + l] = acc[u][bb];
    __syncwarp();
    float s = 0.f;
    #pragma unroll
    for (int j = 0; j < 32; j++) s += red[(w * 32 + l) * 33 + j];

    int o = o0 + (l >> 3);
    int bb = l & 7;
    s += bias[o];
    if (ACT == 1) {
        s = fmaf(bn_g[o] * (s - bn_m[o]), rsqrtf(bn_v[o] + 1e-5f), bn_b[o]);
        s = (s >= 0.f) ? s : 0.2f * s;
    }
    Y[(size_t)(bg * 8 + bb) * YS + o] = s;
}

// ================= base: g_base[b][c] += g2qc[b][k-chunk] @ red_w[k-chunk][c] (atomic) =================
__global__ __launch_bounds__(256) void base_kernel(const float* __restrict__ red_w) {
    __shared__ float Xs[16][128];
    int k0 = blockIdx.x * 128;
    int c0 = blockIdx.y * 128;
    int bh = blockIdx.z * 16;
    int tid = threadIdx.x;
    int c = tid & 127, brow = tid >> 7;

    for (int q = tid; q < 16 * 128; q += 256) {
        int bb = q >> 7, k = q & 127;
        Xs[bb][k] = g_g2qc[(size_t)(bh + bb) * 1408 + k0 + k];
    }
    __syncthreads();

    float acc[8];
    #pragma unroll
    for (int bb = 0; bb < 8; bb++) acc[bb] = 0.f;
    const float* wp = red_w + (size_t)k0 * Cn + c0 + c;
    #pragma unroll 4
    for (int k = 0; k < 128; k++) {
        float wv = wp[(size_t)k * Cn];
        #pragma unroll
        for (int bb = 0; bb < 8; bb++)
            acc[bb] = fmaf(Xs[brow * 8 + bb][k], wv, acc[bb]);
    }
    #pragma unroll
    for (int bb = 0; bb < 8; bb++)
        atomicAdd(&g_base[(size_t)(bh + brow * 8 + bb) * Cn + c0 + c], acc[bb]);
}

// ================= out =================
__global__ void out_kernel(const float* __restrict__ red_w, const float* __restrict__ red_b,
                           const float* __restrict__ coarse, float* __restrict__ out) {
    int gid = blockIdx.x * blockDim.x + threadIdx.x;
    if (gid >= Bn * Mn * (Cn / 4)) return;
    int qd = gid % (Cn / 4);
    int bm = gid / (Cn / 4);
    int b = bm / Mn;
    int c = qd * 4;

    float4 acc = *(const float4*)(g_base + b * Cn + c);
    float4 rb  = *(const float4*)(red_b + c);
    acc.x += rb.x; acc.y += rb.y; acc.z += rb.z; acc.w += rb.w;
    float c0 = coarse[bm * 3 + 0];
    float c1 = coarse[bm * 3 + 1];
    float c2 = coarse[bm * 3 + 2];
    float4 w0 = *(const float4*)(red_w + (size_t)1408 * Cn + c);
    float4 w1 = *(const float4*)(red_w + (size_t)1409 * Cn + c);
    float4 w2 = *(const float4*)(red_w + (size_t)1410 * Cn + c);
    acc.x += c0 * w0.x + c1 * w1.x + c2 * w2.x;
    acc.y += c0 * w0.y + c1 * w1.y + c2 * w2.y;
    acc.z += c0 * w0.z + c1 * w1.z + c2 * w2.z;
    acc.w += c0 * w0.w + c1 * w1.w + c2 * w2.w;
    *(float4*)(out + (size_t)bm * Cn + c) = acc;
}

// ---------------- launch ----------------
extern "C" void kernel_launch(void* const* d_in, const int* in_sizes, int n_in,
                              void* d_out, int out_size) {
    (void)in_sizes; (void)n_in; (void)out_size;
    const float* coarse     = (const float*)d_in[1];
    const float* skeleton   = (const float*)d_in[2];
    const float* gc1_wroot  = (const float*)d_in[3];
    const float* gc1_wrel   = (const float*)d_in[4];
    const float* gc1_b      = (const float*)d_in[5];
    const float* gc2_wroot  = (const float*)d_in[6];
    const float* gc2_wrel   = (const float*)d_in[7];
    const float* gc2_b      = (const float*)d_in[8];
    const float* proj_w     = (const float*)d_in[9];
    const float* proj_b     = (const float*)d_in[10];
    const float* attn_in_w  = (const float*)d_in[11];
    const float* attn_in_b  = (const float*)d_in[12];
    const float* attn_out_w = (const float*)d_in[13];
    const float* attn_out_b = (const float*)d_in[14];
    const float* inc1_w     = (const float*)d_in[15];
    const float* inc1_b     = (const float*)d_in[16];
    const float* bn_g       = (const float*)d_in[17];
    const float* bn_b       = (const float*)d_in[18];
    const float* bn_m       = (const float*)d_in[19];
    const float* bn_v       = (const float*)d_in[20];
    const float* inc2_w     = (const float*)d_in[21];
    const float* inc2_b     = (const float*)d_in[22];
    const float* red_w      = (const float*)d_in[23];
    const float* red_b      = (const float*)d_in[24];
    float* out = (float*)d_out;

    void *p_g2qc, *p_g1;
    cudaGetSymbolAddress(&p_g2qc, g_g2qc);
    cudaGetSymbolAddress(&p_g1, g_g1);
    float* f_g2qc = (float*)p_g2qc;
    float* f_g1 = (float*)p_g1;

    knn_gc1_kernel<<<dim3(Bn, 5), 512>>>(skeleton, gc1_wroot, gc1_wrel, gc1_b,
                                         proj_w, attn_in_w, attn_out_w, inc1_w, inc2_w, red_w);
    gc2_kernel<<<128, 256>>>(gc2_wroot, gc2_wrel, gc2_b);
    chain1_kernel<<<Bn, Cn>>>(proj_w, proj_b, attn_in_w, attn_in_b, attn_out_w, attn_out_b);

    stageM_kernel<384, 1><<<dim3(32, 4), 256>>>(f_g2qc + 1024, 1408, inc1_w, inc1_b,
                                                f_g1, 1024, bn_g, bn_b, bn_m, bn_v);
    stageM_kernel<1024, 0><<<dim3(32, 4), 256>>>(f_g1, 1024, inc2_w, inc2_b,
                                                 f_g2qc, 1408, nullptr, nullptr, nullptr, nullptr);
    base_kernel<<<dim3(11, 3, 2), 256>>>(red_w);

    out_kernel<<<(Bn * Mn * (Cn / 4) + 255) / 256, 256>>>(red_w, red_b, coarse, out);
}

// round 9
// speedup vs baseline: 1.2051x; 1.2051x over previous
#include <cuda_runtime.h>
#include <cstdint>

// ---------------- constants ----------------
#define Bn 32
#define Mn 448
#define Cn 384
#define Sn 512
#define SDn 128
#define Kn 8
#define NROWS (Bn * Sn)   // 16384

#define AS_STRIDE 132
#define WS_STRIDE 136
#define GC2_SMEM ((128 * AS_STRIDE + 128 * WS_STRIDE) * 4)

// ---------------- scratch ----------------
__device__ int      g_idx[NROWS * Kn];
__device__ float    g_X[NROWS * 64];         // h1(relu), stride 64
__device__ unsigned g_proxy[Bn * SDn];       // encoded float max
__device__ float    g_g2qc[Bn * 1408];       // [0:1024]=g2, [1024:1408]=qc
__device__ float    g_g1[Bn * 1024];
__device__ float    g_base[Bn * Cn];         // atomic-accumulated base (excl. red_b)

// ---------------- helpers ----------------
__device__ __forceinline__ unsigned fenc(float f) {
    unsigned u = __float_as_uint(f);
    return (u & 0x80000000u) ? ~u : (u | 0x80000000u);
}
__device__ __forceinline__ float fdec(unsigned e) {
    unsigned u = (e & 0x80000000u) ? (e ^ 0x80000000u) : ~e;
    return __uint_as_float(u);
}
__device__ __forceinline__ float to_tf32(float x) {
    float r;
    asm("cvt.rna.tf32.f32 %0, %1;" : "=f"(r) : "f"(x));
    return r;
}
__device__ __forceinline__ void mma_tf32(float* c, const uint32_t* a, uint32_t b0, uint32_t b1) {
    asm volatile(
        "mma.sync.aligned.m16n8k8.row.col.f32.tf32.tf32.f32 "
        "{%0,%1,%2,%3}, {%4,%5,%6,%7}, {%8,%9}, {%0,%1,%2,%3};\n"
        : "+f"(c[0]), "+f"(c[1]), "+f"(c[2]), "+f"(c[3])
        : "r"(a[0]), "r"(a[1]), "r"(a[2]), "r"(a[3]), "r"(b0), "r"(b1));
}

// ================= K0: fused knn + gc1 =================
__global__ __launch_bounds__(512) void knn_gc1_kernel(const float* __restrict__ skel,
                                                      const float* __restrict__ wroot,
                                                      const float* __restrict__ wrel,
                                                      const float* __restrict__ bias) {
    __shared__ float sx[Sn], sy[Sn], sz[Sn];
    __shared__ float cd[128 * 32];
    __shared__ int   ci[128 * 32];
    __shared__ float wgt[448];
    int b = blockIdx.x;
    int t = threadIdx.x;
    const float* sk = skel + (size_t)b * Sn * 3;

    #pragma unroll
    for (int q = t; q < Sn * 3; q += 512) {
        float v = sk[q];
        int idx = q / 3, r = q - idx * 3;
        if (r == 0) sx[idx] = v; else if (r == 1) sy[idx] = v; else sz[idx] = v;
    }
    if (blockIdx.y == 0 && t < SDn) g_proxy[b * SDn + t] = 0u;
    if (t < 448) wgt[t] = (t < 192) ? wroot[t] : ((t < 384) ? wrel[t - 192] : bias[t - 384]);
    __syncthreads();

    int p = t >> 2, s4 = t & 3;
    int i = blockIdx.y * 128 + p;
    float xi = sx[i], yi = sy[i], zi = sz[i];

    float bd[8]; int bi8[8];
    #pragma unroll
    for (int k = 0; k < 8; k++) { bd[k] = 3.0e38f; bi8[k] = 0; }

    for (int jj = 0; jj < 128; jj++) {
        int j = jj * 4 + s4;
        float dx = xi - sx[j], dy = yi - sy[j], dz = zi - sz[j];
        float d = fmaf(dx, dx, fmaf(dy, dy, dz * dz));
        if (j == i) d = 3.0e38f;
        if (d < bd[7]) {
            bd[7] = d; bi8[7] = j;
            #pragma unroll
            for (int k = 7; k > 0; k--) {
                if (bd[k] < bd[k - 1]) {
                    float td = bd[k]; bd[k] = bd[k - 1]; bd[k - 1] = td;
                    int ti = bi8[k]; bi8[k] = bi8[k - 1]; bi8[k - 1] = ti;
                }
            }
        }
    }
    #pragma unroll
    for (int k = 0; k < 8; k++) { cd[p * 32 + s4 * 8 + k] = bd[k]; ci[p * 32 + s4 * 8 + k] = bi8[k]; }
    __syncthreads();

    if (t < 128) {
        float fd[8]; int fi[8];
        #pragma unroll
        for (int k = 0; k < 8; k++) { fd[k] = 3.0e38f; fi[k] = 0; }
        for (int s = 0; s < 4; s++) {
            #pragma unroll
            for (int k = 0; k < 8; k++) {
                float d = cd[t * 32 + s * 8 + k];
                if (d >= fd[7]) break;
                int j = ci[t * 32 + s * 8 + k];
                fd[7] = d; fi[7] = j;
                #pragma unroll
                for (int m = 7; m > 0; m--) {
                    if (fd[m] < fd[m - 1]) {
                        float td = fd[m]; fd[m] = fd[m - 1]; fd[m - 1] = td;
                        int ti = fi[m]; fi[m] = fi[m - 1]; fi[m - 1] = ti;
                    }
                }
            }
        }
        int ip = blockIdx.y * 128 + t;
        int row = b * Sn + ip;
        float a0 = 0.f, a1 = 0.f, a2 = 0.f;
        #pragma unroll
        for (int k = 0; k < 8; k++) {
            int j = fi[k];
            g_idx[row * Kn + k] = j;
            a0 += sx[j]; a1 += sy[j]; a2 += sz[j];
        }
        float x0 = sx[ip], x1 = sy[ip], x2 = sz[ip];
        float* cif = (float*)ci;
        #pragma unroll
        for (int ch = 0; ch < 64; ch++) {
            float h = wgt[384 + ch];
            h = fmaf(x0, wgt[0 * 64 + ch], h);
            h = fmaf(x1, wgt[1 * 64 + ch], h);
            h = fmaf(x2, wgt[2 * 64 + ch], h);
            h = fmaf(a0, wgt[192 + 0 * 64 + ch], h);
            h = fmaf(a1, wgt[192 + 1 * 64 + ch], h);
            h = fmaf(a2, wgt[192 + 2 * 64 + ch], h);
            h = fmaxf(h, 0.f);
            if (ch < 32) cd[t * 32 + ch] = h; else cif[t * 32 + ch - 32] = h;
        }
    }
    __syncthreads();

    float* cif = (float*)ci;
    #pragma unroll
    for (int q = t; q < 128 * 64; q += 512) {
        int p2 = q >> 6, ch = q & 63;
        float v = (ch < 32) ? cd[p2 * 32 + ch] : cif[p2 * 32 + ch - 32];
        g_X[(size_t)(b * Sn + blockIdx.y * 128 + p2) * 64 + ch] = v;
    }
}

// ================= K1: gc2 via tf32 mma.sync (fused agg + column max) =================
// grid 128 (one 128-row tile, 4 per batch), block 256 (8 warps, 4x2 warp grid)
__global__ __launch_bounds__(256) void gc2_tf32_kernel(const float* __restrict__ wroot2,
                                                       const float* __restrict__ wrel2,
                                                       const float* __restrict__ b2) {
    extern __shared__ float dsm[];
    float* As = dsm;                    // [128 rows][AS_STRIDE], cols 0..63 h1, 64..127 agg
    float* Ws = dsm + 128 * AS_STRIDE;  // [128 k][WS_STRIDE]
    int r0 = blockIdx.x * 128;
    int b = r0 >> 9;
    int tid = threadIdx.x;

    // ---- fill Ws: 128x128 weights (tf32-rounded) ----
    #pragma unroll
    for (int it = 0; it < 16; it++) {
        int q = it * 256 + tid;          // float4 index, 0..4095
        int k = q >> 5, c4 = q & 31;
        const float* src = (k < 64) ? (wroot2 + (size_t)k * 128 + c4 * 4)
                                    : (wrel2 + (size_t)(k - 64) * 128 + c4 * 4);
        float4 v = *(const float4*)src;
        float* dst = Ws + k * WS_STRIDE + c4 * 4;
        dst[0] = to_tf32(v.x); dst[1] = to_tf32(v.y);
        dst[2] = to_tf32(v.z); dst[3] = to_tf32(v.w);
    }
    // ---- fill As cols 0..63 from h1 (coalesced) ----
    #pragma unroll
    for (int it = 0; it < 8; it++) {
        int q = it * 256 + tid;          // 0..2047
        int row = q >> 4, c4 = q & 15;
        float4 v = *(const float4*)(g_X + (size_t)(r0 + row) * 64 + c4 * 4);
        float* dst = As + row * AS_STRIDE + c4 * 4;
        dst[0] = to_tf32(v.x); dst[1] = to_tf32(v.y);
        dst[2] = to_tf32(v.z); dst[3] = to_tf32(v.w);
    }
    // ---- gather agg into As cols 64..127 (coalesced float4 per neighbor row) ----
    #pragma unroll
    for (int it = 0; it < 8; it++) {
        int q = it * 256 + tid;
        int row = q >> 4, c4 = q & 15;
        const int* id = g_idx + (size_t)(r0 + row) * Kn;
        float ax = 0.f, ay = 0.f, az = 0.f, aw = 0.f;
        #pragma unroll
        for (int n = 0; n < 8; n++) {
            int j = id[n];
            float4 v = *(const float4*)(g_X + (size_t)(b * 512 + j) * 64 + c4 * 4);
            ax += v.x; ay += v.y; az += v.z; aw += v.w;
        }
        float* dst = As + row * AS_STRIDE + 64 + c4 * 4;
        dst[0] = to_tf32(ax); dst[1] = to_tf32(ay);
        dst[2] = to_tf32(az); dst[3] = to_tf32(aw);
    }
    __syncthreads();

    // ---- mma: warp (wr 0..3, wc 0..1) computes rows wr*32..+32, cols wc*64..+64 ----
    int lane = tid & 31, warp = tid >> 5;
    int wr = warp >> 1, wc = warp & 1;
    int mbase = wr * 32, nbase = wc * 64;
    int g = lane >> 2, tg = lane & 3;

    float acc[2][8][4];
    #pragma unroll
    for (int mt = 0; mt < 2; mt++)
        #pragma unroll
        for (int nt = 0; nt < 8; nt++)
            #pragma unroll
            for (int r = 0; r < 4; r++) acc[mt][nt][r] = 0.f;

    #pragma unroll
    for (int ks = 0; ks < 16; ks++) {
        int k0 = ks * 8;
        uint32_t a[2][4];
        #pragma unroll
        for (int mt = 0; mt < 2; mt++) {
            const float* Ab = As + (size_t)(mbase + mt * 16 + g) * AS_STRIDE + k0 + tg;
            a[mt][0] = __float_as_uint(Ab[0]);
            a[mt][1] = __float_as_uint(Ab[8 * AS_STRIDE]);
            a[mt][2] = __float_as_uint(Ab[4]);
            a[mt][3] = __float_as_uint(Ab[8 * AS_STRIDE + 4]);
        }
        #pragma unroll
        for (int nt = 0; nt < 8; nt++) {
            const float* Bb = Ws + (size_t)(k0 + tg) * WS_STRIDE + nbase + nt * 8 + g;
            uint32_t b0 = __float_as_uint(Bb[0]);
            uint32_t b1 = __float_as_uint(Bb[4 * WS_STRIDE]);
            mma_tf32(acc[0][nt], a[0], b0, b1);
            mma_tf32(acc[1][nt], a[1], b0, b1);
        }
    }
    __syncthreads();   // done reading As/Ws; reuse As as colmax scratch

    // ---- per-warp column max: rows covered = g, g+8 (mt0) and +16 (mt1) ----
    float* colmax = As;   // [4 wr][128 cols]
    #pragma unroll
    for (int nt = 0; nt < 8; nt++) {
        #pragma unroll
        for (int j = 0; j < 2; j++) {
            float m = fmaxf(fmaxf(acc[0][nt][j], acc[0][nt][j + 2]),
                            fmaxf(acc[1][nt][j], acc[1][nt][j + 2]));
            #pragma unroll
            for (int off = 4; off < 32; off <<= 1)
                m = fmaxf(m, __shfl_xor_sync(0xffffffffu, m, off));
            if (g == 0) {   // lanes 0..3 hold tg = lane
                int col = nbase + nt * 8 + 2 * tg + j;
                colmax[wr * 128 + col] = m;
            }
        }
    }
    __syncthreads();
    if (tid < 128) {
        float m = colmax[tid];
        #pragma unroll
        for (int t2 = 1; t2 < 4; t2++) m = fmaxf(m, colmax[t2 * 128 + tid]);
        m += b2[tid];
        atomicMax(&g_proxy[b * SDn + tid], fenc(m));
    }
}

// ================= K2: per-batch chain proxy->kv->vh->qc (+ zero g_base) =================
__global__ __launch_bounds__(384) void chain1_kernel(const float* __restrict__ proj_w, const float* __restrict__ proj_b,
                              const float* __restrict__ attn_in_w, const float* __restrict__ attn_in_b,
                              const float* __restrict__ attn_out_w, const float* __restrict__ attn_out_b) {
    int b = blockIdx.x;
    int tid = threadIdx.x; // 384
    __shared__ float sp[SDn], skv[Cn], svh[Cn];
    if (tid < SDn) sp[tid] = fdec(g_proxy[b * SDn + tid]);
    g_base[b * Cn + tid] = 0.f;
    __syncthreads();

    float acc = proj_b[tid];
    #pragma unroll 8
    for (int k = 0; k < SDn; k++) acc = fmaf(sp[k], proj_w[k * Cn + tid], acc);
    skv[tid] = acc;
    __syncthreads();

    int w = tid >> 5, l = tid & 31;

    for (int t = 0; t < 8; t++) {
        int c0 = w * 32 + t * 4;
        const float* r0 = attn_in_w + (size_t)(2 * Cn + c0) * Cn;
        float p0 = 0.f, p1 = 0.f, p2 = 0.f, p3 = 0.f;
        #pragma unroll
        for (int j = l; j < Cn; j += 32) {
            float s = skv[j];
            p0 = fmaf(s, r0[j], p0);
            p1 = fmaf(s, r0[Cn + j], p1);
            p2 = fmaf(s, r0[2 * Cn + j], p2);
            p3 = fmaf(s, r0[3 * Cn + j], p3);
        }
        #pragma unroll
        for (int off = 16; off; off >>= 1) {
            p0 += __shfl_xor_sync(0xffffffffu, p0, off);
            p1 += __shfl_xor_sync(0xffffffffu, p1, off);
            p2 += __shfl_xor_sync(0xffffffffu, p2, off);
            p3 += __shfl_xor_sync(0xffffffffu, p3, off);
        }
        if (l == 0) {
            svh[c0 + 0] = p0 + attn_in_b[2 * Cn + c0 + 0];
            svh[c0 + 1] = p1 + attn_in_b[2 * Cn + c0 + 1];
            svh[c0 + 2] = p2 + attn_in_b[2 * Cn + c0 + 2];
            svh[c0 + 3] = p3 + attn_in_b[2 * Cn + c0 + 3];
        }
    }
    __syncthreads();

    for (int t = 0; t < 8; t++) {
        int c0 = w * 32 + t * 4;
        const float* r0 = attn_out_w + (size_t)c0 * Cn;
        float p0 = 0.f, p1 = 0.f, p2 = 0.f, p3 = 0.f;
        #pragma unroll
        for (int j = l; j < Cn; j += 32) {
            float s = svh[j];
            p0 = fmaf(s, r0[j], p0);
            p1 = fmaf(s, r0[Cn + j], p1);
            p2 = fmaf(s, r0[2 * Cn + j], p2);
            p3 = fmaf(s, r0[3 * Cn + j], p3);
        }
        #pragma unroll
        for (int off = 16; off; off >>= 1) {
            p0 += __shfl_xor_sync(0xffffffffu, p0, off);
            p1 += __shfl_xor_sync(0xffffffffu, p1, off);
            p2 += __shfl_xor_sync(0xffffffffu, p2, off);
            p3 += __shfl_xor_sync(0xffffffffu, p3, off);
        }
        if (l == 0) {
            g_g2qc[b * 1408 + 1024 + c0 + 0] = p0 + attn_out_b[c0 + 0];
            g_g2qc[b * 1408 + 1024 + c0 + 1] = p1 + attn_out_b[c0 + 1];
            g_g2qc[b * 1408 + 1024 + c0 + 2] = p2 + attn_out_b[c0 + 2];
            g_g2qc[b * 1408 + 1024 + c0 + 3] = p3 + attn_out_b[c0 + 3];
        }
    }
}

// ================= stageM4: Y[4 batches][32 outs/block] = act(X @ W^T + b) =================
// grid (Nout/32, 8 bgroups of 4), block 256 (8 warps, 4 out-rows per warp)
template<int K, int ACT>
__global__ __launch_bounds__(256) void stageM_kernel(const float* __restrict__ X, int XS,
                                                     const float* __restrict__ W,
                                                     const float* __restrict__ bias,
                                                     float* __restrict__ Y, int YS,
                                                     const float* __restrict__ bn_g,
                                                     const float* __restrict__ bn_b,
                                                     const float* __restrict__ bn_m,
                                                     const float* __restrict__ bn_v) {
    constexpr int XQ = K / 4;                  // float4 per batch
    constexpr int RED_FLOATS = 8 * 32 * 33;    // 8448
    constexpr int SMEM_FLOATS = (4 * K > RED_FLOATS) ? 4 * K : RED_FLOATS;
    __shared__ __align__(16) float smem[SMEM_FLOATS];
    float4* Xs = (float4*)smem;
    int tid = threadIdx.x;
    int bg = blockIdx.y;
    int w = tid >> 5, l = tid & 31;

    for (int q = tid; q < 4 * XQ; q += 256) {
        int bb = q / XQ, kq = q % XQ;
        Xs[q] = *(const float4*)(X + (size_t)(bg * 4 + bb) * XS + kq * 4);
    }
    __syncthreads();

    int o0 = blockIdx.x * 32 + w * 4;
    float acc[4][4];
    #pragma unroll
    for (int u = 0; u < 4; u++)
        #pragma unroll
        for (int bb = 0; bb < 4; bb++) acc[u][bb] = 0.f;

    #pragma unroll
    for (int ki = 0; ki < K / 128; ki++) {
        int kq = ki * 32 + l;
        float4 xv[4];
        #pragma unroll
        for (int bb = 0; bb < 4; bb++) xv[bb] = Xs[bb * XQ + kq];
        float4 wv[4];
        #pragma unroll
        for (int u = 0; u < 4; u++)
            wv[u] = *(const float4*)(W + (size_t)(o0 + u) * K + kq * 4);
        #pragma unroll
        for (int u = 0; u < 4; u++)
            #pragma unroll
            for (int bb = 0; bb < 4; bb++) {
                acc[u][bb] = fmaf(wv[u].x, xv[bb].x, acc[u][bb]);
                acc[u][bb] = fmaf(wv[u].y, xv[bb].y, acc[u][bb]);
                acc[u][bb] = fmaf(wv[u].z, xv[bb].z, acc[u][bb]);
                acc[u][bb] = fmaf(wv[u].w, xv[bb].w, acc[u][bb]);
            }
    }
    __syncthreads();   // done with Xs; reuse smem as reduction scratch

    float* red = smem; // rows: w*32 + (u*4+bb), only first 16 of each warp's 32 used
    #pragma unroll
    for (int u = 0; u < 4; u++)
        #pragma unroll
        for (int bb = 0; bb < 4; bb++)
            red[(w * 32 + u * 4 + bb) * 33 + l] = acc[u][bb];
    __syncwarp();
    if (l < 16) {
        float s = 0.f;
        #pragma unroll
        for (int j = 0; j < 32; j++) s += red[(w * 32 + l) * 33 + j];
        int o = o0 + (l >> 2);
        int bb = l & 3;
        s += bias[o];
        if (ACT == 1) {
            s = fmaf(bn_g[o] * (s - bn_m[o]), rsqrtf(bn_v[o] + 1e-5f), bn_b[o]);
            s = (s >= 0.f) ? s : 0.2f * s;
        }
        Y[(size_t)(bg * 4 + bb) * YS + o] = s;
    }
}

// ================= base: g_base[b][c] += g2qc[b][k-chunk] @ red_w[k-chunk][c] (atomic) =================
// grid (11 kchunks, 3 ctiles, 4 bquarters), block 256
__global__ __launch_bounds__(256) void base_kernel(const float* __restrict__ red_w) {
    __shared__ float Xs[8][128];
    int k0 = blockIdx.x * 128;
    int c0 = blockIdx.y * 128;
    int bh = blockIdx.z * 8;
    int tid = threadIdx.x;
    int c = tid & 127, brow = tid >> 7;

    for (int q = tid; q < 8 * 128; q += 256) {
        int bb = q >> 7, k = q & 127;
        Xs[bb][k] = g_g2qc[(size_t)(bh + bb) * 1408 + k0 + k];
    }
    __syncthreads();

    float acc[4];
    #pragma unroll
    for (int bb = 0; bb < 4; bb++) acc[bb] = 0.f;
    const float* wp = red_w + (size_t)k0 * Cn + c0 + c;
    #pragma unroll 4
    for (int k = 0; k < 128; k++) {
        float wv = wp[(size_t)k * Cn];
        #pragma unroll
        for (int bb = 0; bb < 4; bb++)
            acc[bb] = fmaf(Xs[brow * 4 + bb][k], wv, acc[bb]);
    }
    #pragma unroll
    for (int bb = 0; bb < 4; bb++)
        atomicAdd(&g_base[(size_t)(bh + brow * 4 + bb) * Cn + c0 + c], acc[bb]);
}

// ================= out =================
__global__ void out_kernel(const float* __restrict__ red_w, const float* __restrict__ red_b,
                           const float* __restrict__ coarse, float* __restrict__ out) {
    int gid = blockIdx.x * blockDim.x + threadIdx.x;
    if (gid >= Bn * Mn * (Cn / 4)) return;
    int qd = gid % (Cn / 4);
    int bm = gid / (Cn / 4);
    int b = bm / Mn;
    int c = qd * 4;

    float4 acc = *(const float4*)(g_base + b * Cn + c);
    float4 rb  = *(const float4*)(red_b + c);
    acc.x += rb.x; acc.y += rb.y; acc.z += rb.z; acc.w += rb.w;
    float c0 = coarse[bm * 3 + 0];
    float c1 = coarse[bm * 3 + 1];
    float c2 = coarse[bm * 3 + 2];
    float4 w0 = *(const float4*)(red_w + (size_t)1408 * Cn + c);
    float4 w1 = *(const float4*)(red_w + (size_t)1409 * Cn + c);
    float4 w2 = *(const float4*)(red_w + (size_t)1410 * Cn + c);
    acc.x += c0 * w0.x + c1 * w1.x + c2 * w2.x;
    acc.y += c0 * w0.y + c1 * w1.y + c2 * w2.y;
    acc.z += c0 * w0.z + c1 * w1.z + c2 * w2.z;
    acc.w += c0 * w0.w + c1 * w1.w + c2 * w2.w;
    *(float4*)(out + (size_t)bm * Cn + c) = acc;
}

// ---------------- launch ----------------
extern "C" void kernel_launch(void* const* d_in, const int* in_sizes, int n_in,
                              void* d_out, int out_size) {
    (void)in_sizes; (void)n_in; (void)out_size;
    const float* coarse     = (const float*)d_in[1];
    const float* skeleton   = (const float*)d_in[2];
    const float* gc1_wroot  = (const float*)d_in[3];
    const float* gc1_wrel   = (const float*)d_in[4];
    const float* gc1_b      = (const float*)d_in[5];
    const float* gc2_wroot  = (const float*)d_in[6];
    const float* gc2_wrel   = (const float*)d_in[7];
    const float* gc2_b      = (const float*)d_in[8];
    const float* proj_w     = (const float*)d_in[9];
    const float* proj_b     = (const float*)d_in[10];
    const float* attn_in_w  = (const float*)d_in[11];
    const float* attn_in_b  = (const float*)d_in[12];
    const float* attn_out_w = (const float*)d_in[13];
    const float* attn_out_b = (const float*)d_in[14];
    const float* inc1_w     = (const float*)d_in[15];
    const float* inc1_b     = (const float*)d_in[16];
    const float* bn_g       = (const float*)d_in[17];
    const float* bn_b       = (const float*)d_in[18];
    const float* bn_m       = (const float*)d_in[19];
    const float* bn_v       = (const float*)d_in[20];
    const float* inc2_w     = (const float*)d_in[21];
    const float* inc2_b     = (const float*)d_in[22];
    const float* red_w      = (const float*)d_in[23];
    const float* red_b      = (const float*)d_in[24];
    float* out = (float*)d_out;

    void *p_g2qc, *p_g1;
    cudaGetSymbolAddress(&p_g2qc, g_g2qc);
    cudaGetSymbolAddress(&p_g1, g_g1);
    float* f_g2qc = (float*)p_g2qc;
    float* f_g1 = (float*)p_g1;

    static int smem_set = 0;
    if (!smem_set) {
        cudaFuncSetAttribute(gc2_tf32_kernel, cudaFuncAttributeMaxDynamicSharedMemorySize, GC2_SMEM);
        smem_set = 1;
    }

    knn_gc1_kernel<<<dim3(Bn, 4), 512>>>(skeleton, gc1_wroot, gc1_wrel, gc1_b);
    gc2_tf32_kernel<<<128, 256, GC2_SMEM>>>(gc2_wroot, gc2_wrel, gc2_b);
    chain1_kernel<<<Bn, Cn>>>(proj_w, proj_b, attn_in_w, attn_in_b, attn_out_w, attn_out_b);

    stageM_kernel<384, 1><<<dim3(32, 8), 256>>>(f_g2qc + 1024, 1408, inc1_w, inc1_b,
                                                f_g1, 1024, bn_g, bn_b, bn_m, bn_v);
    stageM_kernel<1024, 0><<<dim3(32, 8), 256>>>(f_g1, 1024, inc2_w, inc2_b,
                                                 f_g2qc, 1408, nullptr, nullptr, nullptr, nullptr);
    base_kernel<<<dim3(11, 3, 4), 256>>>(red_w);

    out_kernel<<<(Bn * Mn * (Cn / 4) + 255) / 256, 256>>>(red_w, red_b, coarse, out);
}

// round 10
// speedup vs baseline: 1.3279x; 1.1019x over previous
#include <cuda_runtime.h>
#include <cstdint>

// ---------------- constants ----------------
#define Bn 32
#define Mn 448
#define Cn 384
#define Sn 512
#define SDn 128
#define Kn 8
#define NROWS (Bn * Sn)   // 16384
#define NB 148            // mega-kernel grid (1 block/SM resident)

#define AS_STRIDE 132
#define WS_STRIDE 136
#define GC2_SMEM ((128 * AS_STRIDE + 128 * WS_STRIDE) * 4)   // 137216 B

// ---------------- scratch ----------------
__device__ int      g_idx[NROWS * Kn];
__device__ float    g_X[NROWS * 64];         // h1(relu), stride 64
__device__ unsigned g_proxy[Bn * SDn];       // encoded float max
__device__ float    g_kv[Bn * Cn];
__device__ float    g_vh[Bn * Cn];
__device__ float    g_g2qc[Bn * 1408];       // [0:1024]=g2, [1024:1408]=qc
__device__ float    g_g1[Bn * 1024];
__device__ float    g_base[Bn * Cn];         // atomic-accumulated base (excl. red_b)
__device__ unsigned g_count = 0;
__device__ unsigned g_gen = 0;

// ---------------- helpers ----------------
__device__ __forceinline__ unsigned fenc(float f) {
    unsigned u = __float_as_uint(f);
    return (u & 0x80000000u) ? ~u : (u | 0x80000000u);
}
__device__ __forceinline__ float fdec(unsigned e) {
    unsigned u = (e & 0x80000000u) ? (e ^ 0x80000000u) : ~e;
    return __uint_as_float(u);
}
__device__ __forceinline__ float to_tf32(float x) {
    float r;
    asm("cvt.rna.tf32.f32 %0, %1;" : "=f"(r) : "f"(x));
    return r;
}
__device__ __forceinline__ void mma_tf32(float* c, const uint32_t* a, uint32_t b0, uint32_t b1) {
    asm volatile(
        "mma.sync.aligned.m16n8k8.row.col.f32.tf32.tf32.f32 "
        "{%0,%1,%2,%3}, {%4,%5,%6,%7}, {%8,%9}, {%0,%1,%2,%3};\n"
        : "+f"(c[0]), "+f"(c[1]), "+f"(c[2]), "+f"(c[3])
        : "r"(a[0]), "r"(a[1]), "r"(a[2]), "r"(a[3]), "r"(b0), "r"(b1));
}

// generation-counter grid barrier (read gen BEFORE arriving -> race-free)
__device__ __forceinline__ void grid_bar() {
    __syncthreads();
    if (threadIdx.x == 0) {
        unsigned my = *(volatile unsigned*)&g_gen;
        __threadfence();
        if (atomicAdd(&g_count, 1) == NB - 1) {
            g_count = 0;
            __threadfence();
            atomicAdd(&g_gen, 1);
        } else {
            while (*(volatile unsigned*)&g_gen == my) __nanosleep(64);
            __threadfence();
        }
    }
    __syncthreads();
}

// ================= K0: fused knn + gc1 (unchanged) =================
__global__ __launch_bounds__(512) void knn_gc1_kernel(const float* __restrict__ skel,
                                                      const float* __restrict__ wroot,
                                                      const float* __restrict__ wrel,
                                                      const float* __restrict__ bias) {
    __shared__ float sx[Sn], sy[Sn], sz[Sn];
    __shared__ float cd[128 * 32];
    __shared__ int   ci[128 * 32];
    __shared__ float wgt[448];
    int b = blockIdx.x;
    int t = threadIdx.x;
    const float* sk = skel + (size_t)b * Sn * 3;

    #pragma unroll
    for (int q = t; q < Sn * 3; q += 512) {
        float v = sk[q];
        int idx = q / 3, r = q - idx * 3;
        if (r == 0) sx[idx] = v; else if (r == 1) sy[idx] = v; else sz[idx] = v;
    }
    if (blockIdx.y == 0 && t < SDn) g_proxy[b * SDn + t] = 0u;
    if (t < 448) wgt[t] = (t < 192) ? wroot[t] : ((t < 384) ? wrel[t - 192] : bias[t - 384]);
    __syncthreads();

    int p = t >> 2, s4 = t & 3;
    int i = blockIdx.y * 128 + p;
    float xi = sx[i], yi = sy[i], zi = sz[i];

    float bd[8]; int bi8[8];
    #pragma unroll
    for (int k = 0; k < 8; k++) { bd[k] = 3.0e38f; bi8[k] = 0; }

    for (int jj = 0; jj < 128; jj++) {
        int j = jj * 4 + s4;
        float dx = xi - sx[j], dy = yi - sy[j], dz = zi - sz[j];
        float d = fmaf(dx, dx, fmaf(dy, dy, dz * dz));
        if (j == i) d = 3.0e38f;
        if (d < bd[7]) {
            bd[7] = d; bi8[7] = j;
            #pragma unroll
            for (int k = 7; k > 0; k--) {
                if (bd[k] < bd[k - 1]) {
                    float td = bd[k]; bd[k] = bd[k - 1]; bd[k - 1] = td;
                    int ti = bi8[k]; bi8[k] = bi8[k - 1]; bi8[k - 1] = ti;
                }
            }
        }
    }
    #pragma unroll
    for (int k = 0; k < 8; k++) { cd[p * 32 + s4 * 8 + k] = bd[k]; ci[p * 32 + s4 * 8 + k] = bi8[k]; }
    __syncthreads();

    if (t < 128) {
        float fd[8]; int fi[8];
        #pragma unroll
        for (int k = 0; k < 8; k++) { fd[k] = 3.0e38f; fi[k] = 0; }
        for (int s = 0; s < 4; s++) {
            #pragma unroll
            for (int k = 0; k < 8; k++) {
                float d = cd[t * 32 + s * 8 + k];
                if (d >= fd[7]) break;
                int j = ci[t * 32 + s * 8 + k];
                fd[7] = d; fi[7] = j;
                #pragma unroll
                for (int m = 7; m > 0; m--) {
                    if (fd[m] < fd[m - 1]) {
                        float td = fd[m]; fd[m] = fd[m - 1]; fd[m - 1] = td;
                        int ti = fi[m]; fi[m] = fi[m - 1]; fi[m - 1] = ti;
                    }
                }
            }
        }
        int ip = blockIdx.y * 128 + t;
        int row = b * Sn + ip;
        float a0 = 0.f, a1 = 0.f, a2 = 0.f;
        #pragma unroll
        for (int k = 0; k < 8; k++) {
            int j = fi[k];
            g_idx[row * Kn + k] = j;
            a0 += sx[j]; a1 += sy[j]; a2 += sz[j];
        }
        float x0 = sx[ip], x1 = sy[ip], x2 = sz[ip];
        float* cif = (float*)ci;
        #pragma unroll
        for (int ch = 0; ch < 64; ch++) {
            float h = wgt[384 + ch];
            h = fmaf(x0, wgt[0 * 64 + ch], h);
            h = fmaf(x1, wgt[1 * 64 + ch], h);
            h = fmaf(x2, wgt[2 * 64 + ch], h);
            h = fmaf(a0, wgt[192 + 0 * 64 + ch], h);
            h = fmaf(a1, wgt[192 + 1 * 64 + ch], h);
            h = fmaf(a2, wgt[192 + 2 * 64 + ch], h);
            h = fmaxf(h, 0.f);
            if (ch < 32) cd[t * 32 + ch] = h; else cif[t * 32 + ch - 32] = h;
        }
    }
    __syncthreads();

    float* cif = (float*)ci;
    #pragma unroll
    for (int q = t; q < 128 * 64; q += 512) {
        int p2 = q >> 6, ch = q & 63;
        float v = (ch < 32) ? cd[p2 * 32 + ch] : cif[p2 * 32 + ch - 32];
        g_X[(size_t)(b * Sn + blockIdx.y * 128 + p2) * 64 + ch] = v;
    }
}

// ================= K1: MEGA — gc2 + kv + vh + qc + g1 + g2 + base + out =================
__global__ __launch_bounds__(256) void mega_kernel(
    const float* __restrict__ wroot2, const float* __restrict__ wrel2, const float* __restrict__ b2,
    const float* __restrict__ proj_w, const float* __restrict__ proj_b,
    const float* __restrict__ attn_in_w, const float* __restrict__ attn_in_b,
    const float* __restrict__ attn_out_w, const float* __restrict__ attn_out_b,
    const float* __restrict__ inc1_w, const float* __restrict__ inc1_b,
    const float* __restrict__ bn_g, const float* __restrict__ bn_b,
    const float* __restrict__ bn_m, const float* __restrict__ bn_v,
    const float* __restrict__ inc2_w, const float* __restrict__ inc2_b,
    const float* __restrict__ red_w, const float* __restrict__ red_b,
    const float* __restrict__ coarse, float* __restrict__ out)
{
    extern __shared__ float dsm[];
    int tid = threadIdx.x;
    int bid = blockIdx.x;
    int lane = tid & 31, warp = tid >> 5;
    int wgid = bid * 8 + warp;     // 0..1183

    // ===== phase 0: gc2 tf32 (blocks 0..127); idle blocks zero g_base =====
    if (bid < 128) {
        float* As = dsm;
        float* Ws = dsm + 128 * AS_STRIDE;
        int r0 = bid * 128;
        int b = r0 >> 9;

        #pragma unroll
        for (int it = 0; it < 16; it++) {
            int q = it * 256 + tid;
            int k = q >> 5, c4 = q & 31;
            const float* src = (k < 64) ? (wroot2 + (size_t)k * 128 + c4 * 4)
                                        : (wrel2 + (size_t)(k - 64) * 128 + c4 * 4);
            float4 v = *(const float4*)src;
            float* dst = Ws + k * WS_STRIDE + c4 * 4;
            dst[0] = to_tf32(v.x); dst[1] = to_tf32(v.y);
            dst[2] = to_tf32(v.z); dst[3] = to_tf32(v.w);
        }
        #pragma unroll
        for (int it = 0; it < 8; it++) {
            int q = it * 256 + tid;
            int row = q >> 4, c4 = q & 15;
            float4 v = *(const float4*)(g_X + (size_t)(r0 + row) * 64 + c4 * 4);
            float* dst = As + row * AS_STRIDE + c4 * 4;
            dst[0] = to_tf32(v.x); dst[1] = to_tf32(v.y);
            dst[2] = to_tf32(v.z); dst[3] = to_tf32(v.w);
        }
        #pragma unroll
        for (int it = 0; it < 8; it++) {
            int q = it * 256 + tid;
            int row = q >> 4, c4 = q & 15;
            const int* id = g_idx + (size_t)(r0 + row) * Kn;
            float ax = 0.f, ay = 0.f, az = 0.f, aw = 0.f;
            #pragma unroll
            for (int n = 0; n < 8; n++) {
                int j = id[n];
                float4 v = *(const float4*)(g_X + (size_t)(b * 512 + j) * 64 + c4 * 4);
                ax += v.x; ay += v.y; az += v.z; aw += v.w;
            }
            float* dst = As + row * AS_STRIDE + 64 + c4 * 4;
            dst[0] = to_tf32(ax); dst[1] = to_tf32(ay);
            dst[2] = to_tf32(az); dst[3] = to_tf32(aw);
        }
        __syncthreads();

        int wr = warp >> 1, wc = warp & 1;
        int mbase = wr * 32, nbase = wc * 64;
        int g = lane >> 2, tg = lane & 3;

        float acc[2][8][4];
        #pragma unroll
        for (int mt = 0; mt < 2; mt++)
            #pragma unroll
            for (int nt = 0; nt < 8; nt++)
                #pragma unroll
                for (int r = 0; r < 4; r++) acc[mt][nt][r] = 0.f;

        #pragma unroll
        for (int ks = 0; ks < 16; ks++) {
            int k0 = ks * 8;
            uint32_t a[2][4];
            #pragma unroll
            for (int mt = 0; mt < 2; mt++) {
                const float* Ab = As + (size_t)(mbase + mt * 16 + g) * AS_STRIDE + k0 + tg;
                a[mt][0] = __float_as_uint(Ab[0]);
                a[mt][1] = __float_as_uint(Ab[8 * AS_STRIDE]);
                a[mt][2] = __float_as_uint(Ab[4]);
                a[mt][3] = __float_as_uint(Ab[8 * AS_STRIDE + 4]);
            }
            #pragma unroll
            for (int nt = 0; nt < 8; nt++) {
                const float* Bb = Ws + (size_t)(k0 + tg) * WS_STRIDE + nbase + nt * 8 + g;
                uint32_t b0 = __float_as_uint(Bb[0]);
                uint32_t b1 = __float_as_uint(Bb[4 * WS_STRIDE]);
                mma_tf32(acc[0][nt], a[0], b0, b1);
                mma_tf32(acc[1][nt], a[1], b0, b1);
            }
        }
        __syncthreads();

        float* colmax = As;
        #pragma unroll
        for (int nt = 0; nt < 8; nt++) {
            #pragma unroll
            for (int j = 0; j < 2; j++) {
                float m = fmaxf(fmaxf(acc[0][nt][j], acc[0][nt][j + 2]),
                                fmaxf(acc[1][nt][j], acc[1][nt][j + 2]));
                #pragma unroll
                for (int off = 4; off < 32; off <<= 1)
                    m = fmaxf(m, __shfl_xor_sync(0xffffffffu, m, off));
                if (g == 0) {
                    int col = nbase + nt * 8 + 2 * tg + j;
                    colmax[wr * 128 + col] = m;
                }
            }
        }
        __syncthreads();
        if (tid < 128) {
            float m = colmax[tid];
            #pragma unroll
            for (int t2 = 1; t2 < 4; t2++) m = fmaxf(m, colmax[t2 * 128 + tid]);
            m += b2[tid];
            atomicMax(&g_proxy[b * SDn + tid], fenc(m));
        }
    } else {
        int ib = bid - 128;  // 0..19
        for (int q = ib * 256 + tid; q < Bn * Cn; q += 20 * 256) g_base[q] = 0.f;
    }
    grid_bar();

    // ===== phase 1: kv = dec(proxy) @ proj_w + proj_b =====
    {
        int gt = bid * 256 + tid;
        if (gt < Bn * Cn) {
            int b = gt / Cn, c = gt - b * Cn;
            float acc = proj_b[c];
            #pragma unroll 8
            for (int k = 0; k < SDn; k++)
                acc = fmaf(fdec(g_proxy[b * SDn + k]), proj_w[k * Cn + c], acc);
            g_kv[gt] = acc;
        }
    }
    grid_bar();

    // ===== phase 2: vh = kv @ wv^T + bv  (warp per 4 outputs) =====
    for (int t = wgid; t < Bn * 96; t += NB * 8) {
        int b = t / 96, c0 = (t % 96) * 4;
        const float* r0 = attn_in_w + (size_t)(2 * Cn + c0) * Cn;
        const float* kvb = g_kv + b * Cn;
        float p0 = 0.f, p1 = 0.f, p2 = 0.f, p3 = 0.f;
        #pragma unroll
        for (int j = lane; j < Cn; j += 32) {
            float s = kvb[j];
            p0 = fmaf(s, r0[j], p0);
            p1 = fmaf(s, r0[Cn + j], p1);
            p2 = fmaf(s, r0[2 * Cn + j], p2);
            p3 = fmaf(s, r0[3 * Cn + j], p3);
        }
        #pragma unroll
        for (int off = 16; off; off >>= 1) {
            p0 += __shfl_xor_sync(0xffffffffu, p0, off);
            p1 += __shfl_xor_sync(0xffffffffu, p1, off);
            p2 += __shfl_xor_sync(0xffffffffu, p2, off);
            p3 += __shfl_xor_sync(0xffffffffu, p3, off);
        }
        if (lane == 0) {
            g_vh[b * Cn + c0 + 0] = p0 + attn_in_b[2 * Cn + c0 + 0];
            g_vh[b * Cn + c0 + 1] = p1 + attn_in_b[2 * Cn + c0 + 1];
            g_vh[b * Cn + c0 + 2] = p2 + attn_in_b[2 * Cn + c0 + 2];
            g_vh[b * Cn + c0 + 3] = p3 + attn_in_b[2 * Cn + c0 + 3];
        }
    }
    grid_bar();

    // ===== phase 3: qc = vh @ attn_out^T + b =====
    for (int t = wgid; t < Bn * 96; t += NB * 8) {
        int b = t / 96, c0 = (t % 96) * 4;
        const float* r0 = attn_out_w + (size_t)c0 * Cn;
        const float* vhb = g_vh + b * Cn;
        float p0 = 0.f, p1 = 0.f, p2 = 0.f, p3 = 0.f;
        #pragma unroll
        for (int j = lane; j < Cn; j += 32) {
            float s = vhb[j];
            p0 = fmaf(s, r0[j], p0);
            p1 = fmaf(s, r0[Cn + j], p1);
            p2 = fmaf(s, r0[2 * Cn + j], p2);
            p3 = fmaf(s, r0[3 * Cn + j], p3);
        }
        #pragma unroll
        for (int off = 16; off; off >>= 1) {
            p0 += __shfl_xor_sync(0xffffffffu, p0, off);
            p1 += __shfl_xor_sync(0xffffffffu, p1, off);
            p2 += __shfl_xor_sync(0xffffffffu, p2, off);
            p3 += __shfl_xor_sync(0xffffffffu, p3, off);
        }
        if (lane == 0) {
            g_g2qc[b * 1408 + 1024 + c0 + 0] = p0 + attn_out_b[c0 + 0];
            g_g2qc[b * 1408 + 1024 + c0 + 1] = p1 + attn_out_b[c0 + 1];
            g_g2qc[b * 1408 + 1024 + c0 + 2] = p2 + attn_out_b[c0 + 2];
            g_g2qc[b * 1408 + 1024 + c0 + 3] = p3 + attn_out_b[c0 + 3];
        }
    }
    grid_bar();

    // ===== phase 4: g1 = leaky(BN(qc @ inc1^T + b1)); block owns bgroup of 8 =====
    {
        int bg = bid & 3, blkk = bid >> 2;   // 37 blocks per bgroup
        float* sQ = dsm;                      // 8 x 384
        for (int q = tid; q < 8 * Cn; q += 256) {
            int bb = q / Cn, j = q - bb * Cn;
            sQ[q] = g_g2qc[(size_t)(bg * 8 + bb) * 1408 + 1024 + j];
        }
        __syncthreads();
        for (int o = blkk * 8 + warp; o < 1024; o += 296) {
            const float* wr = inc1_w + (size_t)o * Cn;
            float acc[8];
            #pragma unroll
            for (int bb = 0; bb < 8; bb++) acc[bb] = 0.f;
            #pragma unroll
            for (int j = lane; j < Cn; j += 32) {
                float w = wr[j];
                #pragma unroll
                for (int bb = 0; bb < 8; bb++)
                    acc[bb] = fmaf(w, sQ[bb * Cn + j], acc[bb]);
            }
            #pragma unroll
            for (int off = 16; off; off >>= 1)
                #pragma unroll
                for (int bb = 0; bb < 8; bb++)
                    acc[bb] += __shfl_xor_sync(0xffffffffu, acc[bb], off);
            float v = acc[0];
            #pragma unroll
            for (int bb = 1; bb < 8; bb++) if (lane == bb) v = acc[bb];
            if (lane < 8) {
                v += inc1_b[o];
                v = fmaf(bn_g[o] * (v - bn_m[o]), rsqrtf(bn_v[o] + 1e-5f), bn_b[o]);
                v = (v >= 0.f) ? v : 0.2f * v;
                g_g1[(size_t)(bg * 8 + lane) * 1024 + o] = v;
            }
        }
    }
    grid_bar();

    // ===== phase 5: g2 = g1 @ inc2^T + b2 =====
    {
        int bg = bid & 3, blkk = bid >> 2;
        float* sG = dsm;                      // 8 x 1024
        for (int q = tid; q < 8 * 1024; q += 256) {
            int bb = q >> 10, j = q & 1023;
            sG[q] = g_g1[(size_t)(bg * 8 + bb) * 1024 + j];
        }
        __syncthreads();
        for (int o = blkk * 8 + warp; o < 1024; o += 296) {
            const float* wr = inc2_w + (size_t)o * 1024;
            float acc[8];
            #pragma unroll
            for (int bb = 0; bb < 8; bb++) acc[bb] = 0.f;
            #pragma unroll 8
            for (int j = lane; j < 1024; j += 32) {
                float w = wr[j];
                #pragma unroll
                for (int bb = 0; bb < 8; bb++)
                    acc[bb] = fmaf(w, sG[bb * 1024 + j], acc[bb]);
            }
            #pragma unroll
            for (int off = 16; off; off >>= 1)
                #pragma unroll
                for (int bb = 0; bb < 8; bb++)
                    acc[bb] += __shfl_xor_sync(0xffffffffu, acc[bb], off);
            float v = acc[0];
            #pragma unroll
            for (int bb = 1; bb < 8; bb++) if (lane == bb) v = acc[bb];
            if (lane < 8)
                g_g2qc[(size_t)(bg * 8 + lane) * 1408 + o] = v + inc2_b[o];
        }
    }
    grid_bar();

    // ===== phase 6: base += g2qc @ red_w (atomic), 132 block-tasks =====
    if (bid < 132) {
        int kc = bid / 12, rem = bid % 12;
        int ct = rem >> 2, bq = rem & 3;
        int k0 = kc * 128, c0 = ct * 128, bh = bq * 8;
        float* Xs = dsm;                      // 8 x 128
        for (int q = tid; q < 8 * 128; q += 256) {
            int bb = q >> 7, k = q & 127;
            Xs[q] = g_g2qc[(size_t)(bh + bb) * 1408 + k0 + k];
        }
        __syncthreads();
        int c = tid & 127, brow = tid >> 7;
        float acc[4];
        #pragma unroll
        for (int bb = 0; bb < 4; bb++) acc[bb] = 0.f;
        const float* wp = red_w + (size_t)k0 * Cn + c0 + c;
        #pragma unroll 4
        for (int k = 0; k < 128; k++) {
            float wv = wp[(size_t)k * Cn];
            #pragma unroll
            for (int bb = 0; bb < 4; bb++)
                acc[bb] = fmaf(Xs[(brow * 4 + bb) * 128 + k], wv, acc[bb]);
        }
        #pragma unroll
        for (int bb = 0; bb < 4; bb++)
            atomicAdd(&g_base[(size_t)(bh + brow * 4 + bb) * Cn + c0 + c], acc[bb]);
    }
    grid_bar();

    // ===== phase 7: out = base + red_b + coarse @ red_w[1408:1411] =====
    for (int gid = bid * 256 + tid; gid < Bn * Mn * (Cn / 4); gid += NB * 256) {
        int qd = gid % (Cn / 4);
        int bm = gid / (Cn / 4);
        int b = bm / Mn;
        int c = qd * 4;

        float4 acc = *(const float4*)(g_base + b * Cn + c);
        float4 rb  = *(const float4*)(red_b + c);
        acc.x += rb.x; acc.y += rb.y; acc.z += rb.z; acc.w += rb.w;
        float c0 = coarse[bm * 3 + 0];
        float c1 = coarse[bm * 3 + 1];
        float c2 = coarse[bm * 3 + 2];
        float4 w0 = *(const float4*)(red_w + (size_t)1408 * Cn + c);
        float4 w1 = *(const float4*)(red_w + (size_t)1409 * Cn + c);
        float4 w2 = *(const float4*)(red_w + (size_t)1410 * Cn + c);
        acc.x += c0 * w0.x + c1 * w1.x + c2 * w2.x;
        acc.y += c0 * w0.y + c1 * w1.y + c2 * w2.y;
        acc.z += c0 * w0.z + c1 * w1.z + c2 * w2.z;
        acc.w += c0 * w0.w + c1 * w1.w + c2 * w2.w;
        *(float4*)(out + (size_t)bm * Cn + c) = acc;
    }
}

// ---------------- launch ----------------
extern "C" void kernel_launch(void* const* d_in, const int* in_sizes, int n_in,
                              void* d_out, int out_size) {
    (void)in_sizes; (void)n_in; (void)out_size;
    const float* coarse     = (const float*)d_in[1];
    const float* skeleton   = (const float*)d_in[2];
    const float* gc1_wroot  = (const float*)d_in[3];
    const float* gc1_wrel   = (const float*)d_in[4];
    const float* gc1_b      = (const float*)d_in[5];
    const float* gc2_wroot  = (const float*)d_in[6];
    const float* gc2_wrel   = (const float*)d_in[7];
    const float* gc2_b      = (const float*)d_in[8];
    const float* proj_w     = (const float*)d_in[9];
    const float* proj_b     = (const float*)d_in[10];
    const float* attn_in_w  = (const float*)d_in[11];
    const float* attn_in_b  = (const float*)d_in[12];
    const float* attn_out_w = (const float*)d_in[13];
    const float* attn_out_b = (const float*)d_in[14];
    const float* inc1_w     = (const float*)d_in[15];
    const float* inc1_b     = (const float*)d_in[16];
    const float* bn_g       = (const float*)d_in[17];
    const float* bn_b       = (const float*)d_in[18];
    const float* bn_m       = (const float*)d_in[19];
    const float* bn_v       = (const float*)d_in[20];
    const float* inc2_w     = (const float*)d_in[21];
    const float* inc2_b     = (const float*)d_in[22];
    const float* red_w      = (const float*)d_in[23];
    const float* red_b      = (const float*)d_in[24];
    float* out = (float*)d_out;

    static int smem_set = 0;
    if (!smem_set) {
        cudaFuncSetAttribute(mega_kernel, cudaFuncAttributeMaxDynamicSharedMemorySize, GC2_SMEM);
        smem_set = 1;
    }

    knn_gc1_kernel<<<dim3(Bn, 4), 512>>>(skeleton, gc1_wroot, gc1_wrel, gc1_b);
    mega_kernel<<<NB, 256, GC2_SMEM>>>(gc2_wroot, gc2_wrel, gc2_b,
                                       proj_w, proj_b,
                                       attn_in_w, attn_in_b,
                                       attn_out_w, attn_out_b,
                                       inc1_w, inc1_b,
                                       bn_g, bn_b, bn_m, bn_v,
                                       inc2_w, inc2_b,
                                       red_w, red_b,
                                       coarse, out);
}

// round 11
// speedup vs baseline: 1.3608x; 1.0247x over previous
#include <cuda_runtime.h>
#include <cstdint>

// ---------------- constants ----------------
#define Bn 32
#define Mn 448
#define Cn 384
#define Sn 512
#define SDn 128
#define Kn 8
#define NROWS (Bn * Sn)   // 16384
#define NB 148            // mega-kernel grid (1 block/SM resident)
#define NT 512            // mega-kernel block size (16 warps)

#define AS_STRIDE 132
#define WS_STRIDE 136
#define GC2_SMEM ((128 * AS_STRIDE + 128 * WS_STRIDE) * 4)   // 137216 B

// ---------------- scratch ----------------
__device__ int      g_idx[NROWS * Kn];
__device__ float    g_X[NROWS * 64];         // h1(relu), stride 64
__device__ unsigned g_proxy[Bn * SDn];       // encoded float max
__device__ float    g_kv[Bn * Cn];
__device__ float    g_vh[Bn * Cn];
__device__ float    g_g2qc[Bn * 1408];       // [0:1024]=g2, [1024:1408]=qc
__device__ float    g_g1[Bn * 1024];
__device__ float    g_base[Bn * Cn];         // atomic-accumulated base (excl. red_b)
__device__ unsigned g_count = 0;
__device__ unsigned g_gen = 0;

// ---------------- helpers ----------------
__device__ __forceinline__ unsigned fenc(float f) {
    unsigned u = __float_as_uint(f);
    return (u & 0x80000000u) ? ~u : (u | 0x80000000u);
}
__device__ __forceinline__ float fdec(unsigned e) {
    unsigned u = (e & 0x80000000u) ? (e ^ 0x80000000u) : ~e;
    return __uint_as_float(u);
}
__device__ __forceinline__ float to_tf32(float x) {
    float r;
    asm("cvt.rna.tf32.f32 %0, %1;" : "=f"(r) : "f"(x));
    return r;
}
__device__ __forceinline__ void mma_tf32(float* c, const uint32_t* a, uint32_t b0, uint32_t b1) {
    asm volatile(
        "mma.sync.aligned.m16n8k8.row.col.f32.tf32.tf32.f32 "
        "{%0,%1,%2,%3}, {%4,%5,%6,%7}, {%8,%9}, {%0,%1,%2,%3};\n"
        : "+f"(c[0]), "+f"(c[1]), "+f"(c[2]), "+f"(c[3])
        : "r"(a[0]), "r"(a[1]), "r"(a[2]), "r"(a[3]), "r"(b0), "r"(b1));
}

// generation-counter grid barrier (read gen BEFORE arriving -> race-free)
__device__ __forceinline__ void grid_bar() {
    __syncthreads();
    if (threadIdx.x == 0) {
        unsigned my = *(volatile unsigned*)&g_gen;
        __threadfence();
        if (atomicAdd(&g_count, 1) == NB - 1) {
            g_count = 0;
            __threadfence();
            atomicAdd(&g_gen, 1);
        } else {
            while (*(volatile unsigned*)&g_gen == my) __nanosleep(64);
            __threadfence();
        }
    }
    __syncthreads();
}

// ================= K0: fused knn + gc1 (unchanged) =================
__global__ __launch_bounds__(512) void knn_gc1_kernel(const float* __restrict__ skel,
                                                      const float* __restrict__ wroot,
                                                      const float* __restrict__ wrel,
                                                      const float* __restrict__ bias) {
    __shared__ float sx[Sn], sy[Sn], sz[Sn];
    __shared__ float cd[128 * 32];
    __shared__ int   ci[128 * 32];
    __shared__ float wgt[448];
    int b = blockIdx.x;
    int t = threadIdx.x;
    const float* sk = skel + (size_t)b * Sn * 3;

    #pragma unroll
    for (int q = t; q < Sn * 3; q += 512) {
        float v = sk[q];
        int idx = q / 3, r = q - idx * 3;
        if (r == 0) sx[idx] = v; else if (r == 1) sy[idx] = v; else sz[idx] = v;
    }
    if (blockIdx.y == 0 && t < SDn) g_proxy[b * SDn + t] = 0u;
    if (t < 448) wgt[t] = (t < 192) ? wroot[t] : ((t < 384) ? wrel[t - 192] : bias[t - 384]);
    __syncthreads();

    int p = t >> 2, s4 = t & 3;
    int i = blockIdx.y * 128 + p;
    float xi = sx[i], yi = sy[i], zi = sz[i];

    float bd[8]; int bi8[8];
    #pragma unroll
    for (int k = 0; k < 8; k++) { bd[k] = 3.0e38f; bi8[k] = 0; }

    for (int jj = 0; jj < 128; jj++) {
        int j = jj * 4 + s4;
        float dx = xi - sx[j], dy = yi - sy[j], dz = zi - sz[j];
        float d = fmaf(dx, dx, fmaf(dy, dy, dz * dz));
        if (j == i) d = 3.0e38f;
        if (d < bd[7]) {
            bd[7] = d; bi8[7] = j;
            #pragma unroll
            for (int k = 7; k > 0; k--) {
                if (bd[k] < bd[k - 1]) {
                    float td = bd[k]; bd[k] = bd[k - 1]; bd[k - 1] = td;
                    int ti = bi8[k]; bi8[k] = bi8[k - 1]; bi8[k - 1] = ti;
                }
            }
        }
    }
    #pragma unroll
    for (int k = 0; k < 8; k++) { cd[p * 32 + s4 * 8 + k] = bd[k]; ci[p * 32 + s4 * 8 + k] = bi8[k]; }
    __syncthreads();

    if (t < 128) {
        float fd[8]; int fi[8];
        #pragma unroll
        for (int k = 0; k < 8; k++) { fd[k] = 3.0e38f; fi[k] = 0; }
        for (int s = 0; s < 4; s++) {
            #pragma unroll
            for (int k = 0; k < 8; k++) {
                float d = cd[t * 32 + s * 8 + k];
                if (d >= fd[7]) break;
                int j = ci[t * 32 + s * 8 + k];
                fd[7] = d; fi[7] = j;
                #pragma unroll
                for (int m = 7; m > 0; m--) {
                    if (fd[m] < fd[m - 1]) {
                        float td = fd[m]; fd[m] = fd[m - 1]; fd[m - 1] = td;
                        int ti = fi[m]; fi[m] = fi[m - 1]; fi[m - 1] = ti;
                    }
                }
            }
        }
        int ip = blockIdx.y * 128 + t;
        int row = b * Sn + ip;
        float a0 = 0.f, a1 = 0.f, a2 = 0.f;
        #pragma unroll
        for (int k = 0; k < 8; k++) {
            int j = fi[k];
            g_idx[row * Kn + k] = j;
            a0 += sx[j]; a1 += sy[j]; a2 += sz[j];
        }
        float x0 = sx[ip], x1 = sy[ip], x2 = sz[ip];
        float* cif = (float*)ci;
        #pragma unroll
        for (int ch = 0; ch < 64; ch++) {
            float h = wgt[384 + ch];
            h = fmaf(x0, wgt[0 * 64 + ch], h);
            h = fmaf(x1, wgt[1 * 64 + ch], h);
            h = fmaf(x2, wgt[2 * 64 + ch], h);
            h = fmaf(a0, wgt[192 + 0 * 64 + ch], h);
            h = fmaf(a1, wgt[192 + 1 * 64 + ch], h);
            h = fmaf(a2, wgt[192 + 2 * 64 + ch], h);
            h = fmaxf(h, 0.f);
            if (ch < 32) cd[t * 32 + ch] = h; else cif[t * 32 + ch - 32] = h;
        }
    }
    __syncthreads();

    float* cif = (float*)ci;
    #pragma unroll
    for (int q = t; q < 128 * 64; q += 512) {
        int p2 = q >> 6, ch = q & 63;
        float v = (ch < 32) ? cd[p2 * 32 + ch] : cif[p2 * 32 + ch - 32];
        g_X[(size_t)(b * Sn + blockIdx.y * 128 + p2) * 64 + ch] = v;
    }
}

// ================= K1: MEGA (512 threads) — gc2 + kv + vh + qc + g1 + g2 + base + out =================
__global__ __launch_bounds__(NT) void mega_kernel(
    const float* __restrict__ wroot2, const float* __restrict__ wrel2, const float* __restrict__ b2,
    const float* __restrict__ proj_w, const float* __restrict__ proj_b,
    const float* __restrict__ attn_in_w, const float* __restrict__ attn_in_b,
    const float* __restrict__ attn_out_w, const float* __restrict__ attn_out_b,
    const float* __restrict__ inc1_w, const float* __restrict__ inc1_b,
    const float* __restrict__ bn_g, const float* __restrict__ bn_b,
    const float* __restrict__ bn_m, const float* __restrict__ bn_v,
    const float* __restrict__ inc2_w, const float* __restrict__ inc2_b,
    const float* __restrict__ red_w, const float* __restrict__ red_b,
    const float* __restrict__ coarse, float* __restrict__ out)
{
    extern __shared__ float dsm[];
    int tid = threadIdx.x;
    int bid = blockIdx.x;
    int lane = tid & 31, warp = tid >> 5;      // warp 0..15
    int wgid = bid * 16 + warp;                // 0..2367

    // ===== phase 0: gc2 tf32 (blocks 0..127); idle blocks zero g_base =====
    if (bid < 128) {
        float* As = dsm;
        float* Ws = dsm + 128 * AS_STRIDE;
        int r0 = bid * 128;
        int b = r0 >> 9;

        #pragma unroll
        for (int it = 0; it < 8; it++) {
            int q = it * NT + tid;           // float4 index, 0..4095
            int k = q >> 5, c4 = q & 31;
            const float* src = (k < 64) ? (wroot2 + (size_t)k * 128 + c4 * 4)
                                        : (wrel2 + (size_t)(k - 64) * 128 + c4 * 4);
            float4 v = *(const float4*)src;
            float* dst = Ws + k * WS_STRIDE + c4 * 4;
            dst[0] = to_tf32(v.x); dst[1] = to_tf32(v.y);
            dst[2] = to_tf32(v.z); dst[3] = to_tf32(v.w);
        }
        #pragma unroll
        for (int it = 0; it < 4; it++) {
            int q = it * NT + tid;           // 0..2047
            int row = q >> 4, c4 = q & 15;
            float4 v = *(const float4*)(g_X + (size_t)(r0 + row) * 64 + c4 * 4);
            float* dst = As + row * AS_STRIDE + c4 * 4;
            dst[0] = to_tf32(v.x); dst[1] = to_tf32(v.y);
            dst[2] = to_tf32(v.z); dst[3] = to_tf32(v.w);
        }
        #pragma unroll
        for (int it = 0; it < 4; it++) {
            int q = it * NT + tid;
            int row = q >> 4, c4 = q & 15;
            const int* id = g_idx + (size_t)(r0 + row) * Kn;
            float ax = 0.f, ay = 0.f, az = 0.f, aw = 0.f;
            #pragma unroll
            for (int n = 0; n < 8; n++) {
                int j = id[n];
                float4 v = *(const float4*)(g_X + (size_t)(b * 512 + j) * 64 + c4 * 4);
                ax += v.x; ay += v.y; az += v.z; aw += v.w;
            }
            float* dst = As + row * AS_STRIDE + 64 + c4 * 4;
            dst[0] = to_tf32(ax); dst[1] = to_tf32(ay);
            dst[2] = to_tf32(az); dst[3] = to_tf32(aw);
        }
        __syncthreads();

        // 16 warps: 4x4 grid; warp computes rows wr*32..+32, cols wc*32..+32
        int wr = warp >> 2, wc = warp & 3;
        int mbase = wr * 32, nbase = wc * 32;
        int g = lane >> 2, tg = lane & 3;

        float acc[2][4][4];
        #pragma unroll
        for (int mt = 0; mt < 2; mt++)
            #pragma unroll
            for (int nt = 0; nt < 4; nt++)
                #pragma unroll
                for (int r = 0; r < 4; r++) acc[mt][nt][r] = 0.f;

        #pragma unroll
        for (int ks = 0; ks < 16; ks++) {
            int k0 = ks * 8;
            uint32_t a[2][4];
            #pragma unroll
            for (int mt = 0; mt < 2; mt++) {
                const float* Ab = As + (size_t)(mbase + mt * 16 + g) * AS_STRIDE + k0 + tg;
                a[mt][0] = __float_as_uint(Ab[0]);
                a[mt][1] = __float_as_uint(Ab[8 * AS_STRIDE]);
                a[mt][2] = __float_as_uint(Ab[4]);
                a[mt][3] = __float_as_uint(Ab[8 * AS_STRIDE + 4]);
            }
            #pragma unroll
            for (int nt = 0; nt < 4; nt++) {
                const float* Bb = Ws + (size_t)(k0 + tg) * WS_STRIDE + nbase + nt * 8 + g;
                uint32_t b0 = __float_as_uint(Bb[0]);
                uint32_t b1 = __float_as_uint(Bb[4 * WS_STRIDE]);
                mma_tf32(acc[0][nt], a[0], b0, b1);
                mma_tf32(acc[1][nt], a[1], b0, b1);
            }
        }
        __syncthreads();

        float* colmax = As;    // [4 wr][128 cols]
        #pragma unroll
        for (int nt = 0; nt < 4; nt++) {
            #pragma unroll
            for (int j = 0; j < 2; j++) {
                float m = fmaxf(fmaxf(acc[0][nt][j], acc[0][nt][j + 2]),
                                fmaxf(acc[1][nt][j], acc[1][nt][j + 2]));
                #pragma unroll
                for (int off = 4; off < 32; off <<= 1)
                    m = fmaxf(m, __shfl_xor_sync(0xffffffffu, m, off));
                if (g == 0) {
                    int col = nbase + nt * 8 + 2 * tg + j;
                    colmax[wr * 128 + col] = m;
                }
            }
        }
        __syncthreads();
        if (tid < 128) {
            float m = colmax[tid];
            #pragma unroll
            for (int t2 = 1; t2 < 4; t2++) m = fmaxf(m, colmax[t2 * 128 + tid]);
            m += b2[tid];
            atomicMax(&g_proxy[b * SDn + tid], fenc(m));
        }
    } else {
        int ib = bid - 128;  // 0..19
        for (int q = ib * NT + tid; q < Bn * Cn; q += 20 * NT) g_base[q] = 0.f;
    }
    grid_bar();

    // ===== phase 1: kv = dec(proxy) @ proj_w + proj_b =====
    {
        int gt = bid * NT + tid;
        if (gt < Bn * Cn) {
            int b = gt / Cn, c = gt - b * Cn;
            float acc = proj_b[c];
            #pragma unroll 8
            for (int k = 0; k < SDn; k++)
                acc = fmaf(fdec(g_proxy[b * SDn + k]), proj_w[k * Cn + c], acc);
            g_kv[gt] = acc;
        }
    }
    grid_bar();

    // ===== phase 2: vh = kv @ wv^T + bv  (warp per 4 outputs) =====
    for (int t = wgid; t < Bn * 96; t += NB * 16) {
        int b = t / 96, c0 = (t % 96) * 4;
        const float* r0 = attn_in_w + (size_t)(2 * Cn + c0) * Cn;
        const float* kvb = g_kv + b * Cn;
        float p0 = 0.f, p1 = 0.f, p2 = 0.f, p3 = 0.f;
        #pragma unroll
        for (int j = lane; j < Cn; j += 32) {
            float s = kvb[j];
            p0 = fmaf(s, r0[j], p0);
            p1 = fmaf(s, r0[Cn + j], p1);
            p2 = fmaf(s, r0[2 * Cn + j], p2);
            p3 = fmaf(s, r0[3 * Cn + j], p3);
        }
        #pragma unroll
        for (int off = 16; off; off >>= 1) {
            p0 += __shfl_xor_sync(0xffffffffu, p0, off);
            p1 += __shfl_xor_sync(0xffffffffu, p1, off);
            p2 += __shfl_xor_sync(0xffffffffu, p2, off);
            p3 += __shfl_xor_sync(0xffffffffu, p3, off);
        }
        if (lane == 0) {
            g_vh[b * Cn + c0 + 0] = p0 + attn_in_b[2 * Cn + c0 + 0];
            g_vh[b * Cn + c0 + 1] = p1 + attn_in_b[2 * Cn + c0 + 1];
            g_vh[b * Cn + c0 + 2] = p2 + attn_in_b[2 * Cn + c0 + 2];
            g_vh[b * Cn + c0 + 3] = p3 + attn_in_b[2 * Cn + c0 + 3];
        }
    }
    grid_bar();

    // ===== phase 3: qc = vh @ attn_out^T + b =====
    for (int t = wgid; t < Bn * 96; t += NB * 16) {
        int b = t / 96, c0 = (t % 96) * 4;
        const float* r0 = attn_out_w + (size_t)c0 * Cn;
        const float* vhb = g_vh + b * Cn;
        float p0 = 0.f, p1 = 0.f, p2 = 0.f, p3 = 0.f;
        #pragma unroll
        for (int j = lane; j < Cn; j += 32) {
            float s = vhb[j];
            p0 = fmaf(s, r0[j], p0);
            p1 = fmaf(s, r0[Cn + j], p1);
            p2 = fmaf(s, r0[2 * Cn + j], p2);
            p3 = fmaf(s, r0[3 * Cn + j], p3);
        }
        #pragma unroll
        for (int off = 16; off; off >>= 1) {
            p0 += __shfl_xor_sync(0xffffffffu, p0, off);
            p1 += __shfl_xor_sync(0xffffffffu, p1, off);
            p2 += __shfl_xor_sync(0xffffffffu, p2, off);
            p3 += __shfl_xor_sync(0xffffffffu, p3, off);
        }
        if (lane == 0) {
            g_g2qc[b * 1408 + 1024 + c0 + 0] = p0 + attn_out_b[c0 + 0];
            g_g2qc[b * 1408 + 1024 + c0 + 1] = p1 + attn_out_b[c0 + 1];
            g_g2qc[b * 1408 + 1024 + c0 + 2] = p2 + attn_out_b[c0 + 2];
            g_g2qc[b * 1408 + 1024 + c0 + 3] = p3 + attn_out_b[c0 + 3];
        }
    }
    grid_bar();

    // ===== phase 4: g1 = leaky(BN(qc @ inc1^T + b1)); 4 bgroups x 37 blocks =====
    {
        int bg = bid & 3, blkk = bid >> 2;    // blkk 0..36
        float* sQ = dsm;                       // 8 x 384
        for (int q = tid; q < 8 * Cn; q += NT) {
            int bb = q / Cn, j = q - bb * Cn;
            sQ[q] = g_g2qc[(size_t)(bg * 8 + bb) * 1408 + 1024 + j];
        }
        __syncthreads();
        for (int o = blkk * 16 + warp; o < 1024; o += 592) {
            const float* wr = inc1_w + (size_t)o * Cn;
            float acc[8];
            #pragma unroll
            for (int bb = 0; bb < 8; bb++) acc[bb] = 0.f;
            #pragma unroll
            for (int j = lane; j < Cn; j += 32) {
                float w = wr[j];
                #pragma unroll
                for (int bb = 0; bb < 8; bb++)
                    acc[bb] = fmaf(w, sQ[bb * Cn + j], acc[bb]);
            }
            #pragma unroll
            for (int off = 16; off; off >>= 1)
                #pragma unroll
                for (int bb = 0; bb < 8; bb++)
                    acc[bb] += __shfl_xor_sync(0xffffffffu, acc[bb], off);
            float v = acc[0];
            #pragma unroll
            for (int bb = 1; bb < 8; bb++) if (lane == bb) v = acc[bb];
            if (lane < 8) {
                v += inc1_b[o];
                v = fmaf(bn_g[o] * (v - bn_m[o]), rsqrtf(bn_v[o] + 1e-5f), bn_b[o]);
                v = (v >= 0.f) ? v : 0.2f * v;
                g_g1[(size_t)(bg * 8 + lane) * 1024 + o] = v;
            }
        }
    }
    grid_bar();

    // ===== phase 5: g2 = g1 @ inc2^T + b2 =====
    {
        int bg = bid & 3, blkk = bid >> 2;
        float* sG = dsm;                       // 8 x 1024
        for (int q = tid; q < 8 * 1024; q += NT) {
            int bb = q >> 10, j = q & 1023;
            sG[q] = g_g1[(size_t)(bg * 8 + bb) * 1024 + j];
        }
        __syncthreads();
        for (int o = blkk * 16 + warp; o < 1024; o += 592) {
            const float* wr = inc2_w + (size_t)o * 1024;
            float acc[8];
            #pragma unroll
            for (int bb = 0; bb < 8; bb++) acc[bb] = 0.f;
            #pragma unroll 8
            for (int j = lane; j < 1024; j += 32) {
                float w = wr[j];
                #pragma unroll
                for (int bb = 0; bb < 8; bb++)
                    acc[bb] = fmaf(w, sG[bb * 1024 + j], acc[bb]);
            }
            #pragma unroll
            for (int off = 16; off; off >>= 1)
                #pragma unroll
                for (int bb = 0; bb < 8; bb++)
                    acc[bb] += __shfl_xor_sync(0xffffffffu, acc[bb], off);
            float v = acc[0];
            #pragma unroll
            for (int bb = 1; bb < 8; bb++) if (lane == bb) v = acc[bb];
            if (lane < 8)
                g_g2qc[(size_t)(bg * 8 + lane) * 1408 + o] = v + inc2_b[o];
        }
    }
    grid_bar();

    // ===== phase 6: base += g2qc @ red_w (atomic), 132 block-tasks =====
    if (bid < 132) {
        int kc = bid / 12, rem = bid % 12;
        int ct = rem >> 2, bq = rem & 3;
        int k0 = kc * 128, c0 = ct * 128, bh = bq * 8;
        float* Xs = dsm;                       // 8 x 128
        for (int q = tid; q < 8 * 128; q += NT) {
            int bb = q >> 7, k = q & 127;
            Xs[q] = g_g2qc[(size_t)(bh + bb) * 1408 + k0 + k];
        }
        __syncthreads();
        int c = tid & 127, brow = tid >> 7;    // brow 0..3
        float acc[2];
        acc[0] = 0.f; acc[1] = 0.f;
        const float* wp = red_w + (size_t)k0 * Cn + c0 + c;
        #pragma unroll 4
        for (int k = 0; k < 128; k++) {
            float wv = wp[(size_t)k * Cn];
            acc[0] = fmaf(Xs[(brow * 2 + 0) * 128 + k], wv, acc[0]);
            acc[1] = fmaf(Xs[(brow * 2 + 1) * 128 + k], wv, acc[1]);
        }
        atomicAdd(&g_base[(size_t)(bh + brow * 2 + 0) * Cn + c0 + c], acc[0]);
        atomicAdd(&g_base[(size_t)(bh + brow * 2 + 1) * Cn + c0 + c], acc[1]);
    }
    grid_bar();

    // ===== phase 7: out = base + red_b + coarse @ red_w[1408:1411] =====
    for (int gid = bid * NT + tid; gid < Bn * Mn * (Cn / 4); gid += NB * NT) {
        int qd = gid % (Cn / 4);
        int bm = gid / (Cn / 4);
        int b = bm / Mn;
        int c = qd * 4;

        float4 acc = *(const float4*)(g_base + b * Cn + c);
        float4 rb  = *(const float4*)(red_b + c);
        acc.x += rb.x; acc.y += rb.y; acc.z += rb.z; acc.w += rb.w;
        float c0 = coarse[bm * 3 + 0];
        float c1 = coarse[bm * 3 + 1];
        float c2 = coarse[bm * 3 + 2];
        float4 w0 = *(const float4*)(red_w + (size_t)1408 * Cn + c);
        float4 w1 = *(const float4*)(red_w + (size_t)1409 * Cn + c);
        float4 w2 = *(const float4*)(red_w + (size_t)1410 * Cn + c);
        acc.x += c0 * w0.x + c1 * w1.x + c2 * w2.x;
        acc.y += c0 * w0.y + c1 * w1.y + c2 * w2.y;
        acc.z += c0 * w0.z + c1 * w1.z + c2 * w2.z;
        acc.w += c0 * w0.w + c1 * w1.w + c2 * w2.w;
        *(float4*)(out + (size_t)bm * Cn + c) = acc;
    }
}

// ---------------- launch ----------------
extern "C" void kernel_launch(void* const* d_in, const int* in_sizes, int n_in,
                              void* d_out, int out_size) {
    (void)in_sizes; (void)n_in; (void)out_size;
    const float* coarse     = (const float*)d_in[1];
    const float* skeleton   = (const float*)d_in[2];
    const float* gc1_wroot  = (const float*)d_in[3];
    const float* gc1_wrel   = (const float*)d_in[4];
    const float* gc1_b      = (const float*)d_in[5];
    const float* gc2_wroot  = (const float*)d_in[6];
    const float* gc2_wrel   = (const float*)d_in[7];
    const float* gc2_b      = (const float*)d_in[8];
    const float* proj_w     = (const float*)d_in[9];
    const float* proj_b     = (const float*)d_in[10];
    const float* attn_in_w  = (const float*)d_in[11];
    const float* attn_in_b  = (const float*)d_in[12];
    const float* attn_out_w = (const float*)d_in[13];
    const float* attn_out_b = (const float*)d_in[14];
    const float* inc1_w     = (const float*)d_in[15];
    const float* inc1_b     = (const float*)d_in[16];
    const float* bn_g       = (const float*)d_in[17];
    const float* bn_b       = (const float*)d_in[18];
    const float* bn_m       = (const float*)d_in[19];
    const float* bn_v       = (const float*)d_in[20];
    const float* inc2_w     = (const float*)d_in[21];
    const float* inc2_b     = (const float*)d_in[22];
    const float* red_w      = (const float*)d_in[23];
    const float* red_b      = (const float*)d_in[24];
    float* out = (float*)d_out;

    static int smem_set = 0;
    if (!smem_set) {
        cudaFuncSetAttribute(mega_kernel, cudaFuncAttributeMaxDynamicSharedMemorySize, GC2_SMEM);
        smem_set = 1;
    }

    knn_gc1_kernel<<<dim3(Bn, 4), 512>>>(skeleton, gc1_wroot, gc1_wrel, gc1_b);
    mega_kernel<<<NB, NT, GC2_SMEM>>>(gc2_wroot, gc2_wrel, gc2_b,
                                      proj_w, proj_b,
                                      attn_in_w, attn_in_b,
                                      attn_out_w, attn_out_b,
                                      inc1_w, inc1_b,
                                      bn_g, bn_b, bn_m, bn_v,
                                      inc2_w, inc2_b,
                                      red_w, red_b,
                                      coarse, out);
}